// round 10
// baseline (speedup 1.0000x reference)
#include <cuda_runtime.h>
#include <cuda_bf16.h>
#include <math.h>
#include <stdint.h>

#define NTOK 2048
#define DM 1024
#define HEADS 16
#define DKH 64
#define LOG2E 1.44269504f

typedef __nv_bfloat16 bf16;
typedef __nv_bfloat162 bf162;

// ---------------------------------------------------------------------------
// Scratch (__device__ globals; no allocs allowed)
// ---------------------------------------------------------------------------
__device__ __align__(128) bf16 g_qh[NTOK * DM], g_ql[NTOK * DM];
__device__ __align__(128) bf16 g_kh[NTOK * DM], g_kl[NTOK * DM];
__device__ __align__(128) bf16 g_vh[NTOK * DM], g_vl[NTOK * DM];
__device__ __align__(128) bf16 g_Wqh[DM * DM], g_Wql[DM * DM];
__device__ __align__(128) bf16 g_Wkh[DM * DM], g_Wkl[DM * DM];
__device__ __align__(128) bf16 g_Wvh[DM * DM], g_Wvl[DM * DM];
__device__ __align__(128) bf16 g_Woh[DM * DM], g_Wol[DM * DM];
__device__ __align__(128) bf16 g_Qh[HEADS * NTOK * DKH], g_Ql[HEADS * NTOK * DKH];
__device__ __align__(128) bf16 g_Kh[HEADS * NTOK * DKH], g_Kl[HEADS * NTOK * DKH];
__device__ __align__(128) bf16 g_Vh[HEADS * NTOK * DKH], g_Vl[HEADS * NTOK * DKH];
__device__ __align__(128) bf16 g_Ch[NTOK * DM], g_Cl[NTOK * DM];

// ---------------------------------------------------------------------------
// Warp MMA helpers (base compute_100 features only)
// ---------------------------------------------------------------------------
__device__ __forceinline__ uint32_t smem_u32(const void* p) {
    return (uint32_t)__cvta_generic_to_shared(p);
}

__device__ __forceinline__ void mma_bf16(float c[4], const uint32_t a[4],
                                         uint32_t b0, uint32_t b1) {
    asm volatile(
        "mma.sync.aligned.m16n8k16.row.col.f32.bf16.bf16.f32 "
        "{%0,%1,%2,%3}, {%4,%5,%6,%7}, {%8,%9}, {%0,%1,%2,%3};"
        : "+f"(c[0]), "+f"(c[1]), "+f"(c[2]), "+f"(c[3])
        : "r"(a[0]), "r"(a[1]), "r"(a[2]), "r"(a[3]), "r"(b0), "r"(b1));
}

__device__ __forceinline__ void ldmx4(uint32_t r[4], uint32_t addr) {
    asm volatile(
        "ldmatrix.sync.aligned.m8n8.x4.shared.b16 {%0,%1,%2,%3}, [%4];"
        : "=r"(r[0]), "=r"(r[1]), "=r"(r[2]), "=r"(r[3]) : "r"(addr));
}
__device__ __forceinline__ void ldmx4t(uint32_t r[4], uint32_t addr) {
    asm volatile(
        "ldmatrix.sync.aligned.m8n8.x4.trans.shared.b16 {%0,%1,%2,%3}, [%4];"
        : "=r"(r[0]), "=r"(r[1]), "=r"(r[2]), "=r"(r[3]) : "r"(addr));
}

// Tile format: [rows][64 bf16], row pitch 128B, 16B chunk c swizzled: c ^ (r&7)
__device__ __forceinline__ uint32_t taddr(uint32_t base, int r, int c) {
    return base + r * 128 + (((uint32_t)(c ^ (r & 7))) << 4);
}

__device__ __forceinline__ void ldfragA(uint32_t f[4], uint32_t tb, int row0,
                                        int c0, int lane) {
    int grp = lane >> 3, lr = lane & 7;
    ldmx4(f, taddr(tb, row0 + (grp & 1) * 8 + lr, c0 + (grp >> 1)));
}
__device__ __forceinline__ void ldfragB(uint32_t f[4], uint32_t tb, int n0,
                                        int c0, int lane) {
    int grp = lane >> 3, lr = lane & 7;
    ldmx4(f, taddr(tb, n0 + (grp >> 1) * 8 + lr, c0 + (grp & 1)));
}
__device__ __forceinline__ void ldfragV(uint32_t f[4], uint32_t tb, int k0,
                                        int c0, int lane) {
    int grp = lane >> 3, lr = lane & 7;
    ldmx4t(f, taddr(tb, k0 + (grp & 1) * 8 + lr, c0 + (grp >> 1)));
}

template <int ROWS>
__device__ __forceinline__ void load_tile(uint32_t sbase, const bf16* g,
                                          int pitch, int tid) {
#pragma unroll
    for (int i = 0; i < ROWS * 8 / 256; i++) {
        int idx = i * 256 + tid;
        int r = idx >> 3, c = idx & 7;
        uint32_t dst = taddr(sbase, r, c);
        const void* src = g + (size_t)r * pitch + c * 8;
        asm volatile("cp.async.cg.shared.global [%0], [%1], 16;"
                     :: "r"(dst), "l"(src) : "memory");
    }
}
__device__ __forceinline__ void cp_commit() {
    asm volatile("cp.async.commit_group;" ::: "memory");
}

// ---------------------------------------------------------------------------
// Batched fp32 -> (bf16 hi, bf16 lo) split: 7 jobs, 4 float4 per thread
// ---------------------------------------------------------------------------
struct CvtJobs {
    const float* src[7];
    bf16* hi[7];
    bf16* lo[7];
    int n4[7];
};

__global__ __launch_bounds__(256) void cvt_all(CvtJobs jobs) {
    const int j = blockIdx.y;
    const int n4 = jobs.n4[j];
    const int blk = blockIdx.x * 1024;
    if (blk >= n4) return;
    const int base = blk + threadIdx.x;
    const float4* src = (const float4*)jobs.src[j];

    float4 v[4];
#pragma unroll
    for (int u = 0; u < 4; u++) v[u] = src[base + u * 256];

#pragma unroll
    for (int u = 0; u < 4; u++) {
        int i = base + u * 256;
        bf16 h0 = __float2bfloat16_rn(v[u].x);
        bf16 h1 = __float2bfloat16_rn(v[u].y);
        bf16 h2 = __float2bfloat16_rn(v[u].z);
        bf16 h3 = __float2bfloat16_rn(v[u].w);
        bf162* hp = (bf162*)(jobs.hi[j] + i * 4);
        hp[0] = bf162(h0, h1);
        hp[1] = bf162(h2, h3);
        bf162* lp = (bf162*)(jobs.lo[j] + i * 4);
        lp[0] = bf162(__float2bfloat16_rn(v[u].x - __bfloat162float(h0)),
                      __float2bfloat16_rn(v[u].y - __bfloat162float(h1)));
        lp[1] = bf162(__float2bfloat16_rn(v[u].z - __bfloat162float(h2)),
                      __float2bfloat16_rn(v[u].w - __bfloat162float(h3)));
    }
}

// ---------------------------------------------------------------------------
// bf16x3 NT-GEMM on mma.sync. CTA tile 64x128, warp tile 32x32 (2x4 warps),
// k staged 64, 2-stage cp.async double buffer. 96KB smem -> 2 CTAs/SM.
// MODE 0: fp32 row-major out.  MODE 1: bf16 hi/lo split, head-major, * scale.
// Stage layout: Ah@0 (8K), Al@8K, Bh@16K (16K), Bl@32K.  Stage size 48K.
// ---------------------------------------------------------------------------
#define GEMM_STAGE 49152
#define GEMM_SMEM (2 * GEMM_STAGE)

template <int MODE>
__global__ __launch_bounds__(256, 2) void gemm_mma(
    const bf16* __restrict__ Ah, const bf16* __restrict__ Al,
    const bf16* __restrict__ Bh, const bf16* __restrict__ Bl,
    const float* __restrict__ bias, float* __restrict__ outF,
    bf16* __restrict__ oH, bf16* __restrict__ oL, float scale) {
    extern __shared__ char smem[];
    const uint32_t sbase = smem_u32(smem);
    const int tid = threadIdx.x;
    const int lane = tid & 31;
    const int w = tid >> 5;
    const int wm = w >> 2, wn = w & 3;           // 2 x 4 warps -> 64 x 128
    const int bm = blockIdx.y * 64, bn = blockIdx.x * 128;

    auto load_stage = [&](int kt, int b) {
        uint32_t s0 = sbase + b * GEMM_STAGE;
        load_tile<64> (s0 +     0, Ah + (size_t)bm * DM + kt, DM, tid);
        load_tile<64> (s0 +  8192, Al + (size_t)bm * DM + kt, DM, tid);
        load_tile<128>(s0 + 16384, Bh + (size_t)bn * DM + kt, DM, tid);
        load_tile<128>(s0 + 32768, Bl + (size_t)bn * DM + kt, DM, tid);
        cp_commit();
    };

    float c[2][4][4];
#pragma unroll
    for (int i = 0; i < 2; i++)
#pragma unroll
        for (int j = 0; j < 4; j++)
#pragma unroll
            for (int k = 0; k < 4; k++) c[i][j][k] = 0.f;

    load_stage(0, 0);
    load_stage(64, 1);

    for (int it = 0; it < 16; it++) {
        if (it < 15) asm volatile("cp.async.wait_group 1;" ::: "memory");
        else         asm volatile("cp.async.wait_group 0;" ::: "memory");
        __syncthreads();

        uint32_t s0 = sbase + (it & 1) * GEMM_STAGE;
#pragma unroll
        for (int s = 0; s < 4; s++) {
            uint32_t aH[2][4], aL[2][4], bH[2][4], bL[2][4];
#pragma unroll
            for (int mt = 0; mt < 2; mt++) {
                ldfragA(aH[mt], s0,        wm * 32 + mt * 16, 2 * s, lane);
                ldfragA(aL[mt], s0 + 8192, wm * 32 + mt * 16, 2 * s, lane);
            }
#pragma unroll
            for (int np = 0; np < 2; np++) {
                ldfragB(bH[np], s0 + 16384, wn * 32 + np * 16, 2 * s, lane);
                ldfragB(bL[np], s0 + 32768, wn * 32 + np * 16, 2 * s, lane);
            }
#pragma unroll
            for (int mt = 0; mt < 2; mt++)
#pragma unroll
                for (int np = 0; np < 2; np++)
#pragma unroll
                    for (int hf = 0; hf < 2; hf++) {
                        int nt = np * 2 + hf;
                        mma_bf16(c[mt][nt], aH[mt], bH[np][2 * hf], bH[np][2 * hf + 1]);
                        mma_bf16(c[mt][nt], aH[mt], bL[np][2 * hf], bL[np][2 * hf + 1]);
                        mma_bf16(c[mt][nt], aL[mt], bH[np][2 * hf], bH[np][2 * hf + 1]);
                    }
        }
        __syncthreads();
        // Refill the buffer stage `it` just vacated.
        if (it + 2 < 16) load_stage((it + 2) * 64, it & 1);
    }

#pragma unroll
    for (int mt = 0; mt < 2; mt++)
#pragma unroll
        for (int nt = 0; nt < 4; nt++) {
            int r0 = bm + wm * 32 + mt * 16 + (lane >> 2);
            int col = bn + wn * 32 + nt * 8 + 2 * (lane & 3);
            float b0 = bias[col], b1 = bias[col + 1];
#pragma unroll
            for (int h2 = 0; h2 < 2; h2++) {
                int r = r0 + h2 * 8;
                float x0 = (c[mt][nt][2 * h2]     + b0) * scale;
                float x1 = (c[mt][nt][2 * h2 + 1] + b1) * scale;
                if (MODE == 0) {
                    float2 v = {x0, x1};
                    *(float2*)(outF + (size_t)r * DM + col) = v;
                } else {
                    bf16 h0 = __float2bfloat16_rn(x0);
                    bf16 h1 = __float2bfloat16_rn(x1);
                    size_t off = ((size_t)(col >> 6) * NTOK + r) * DKH + (col & 63);
                    *(bf162*)(oH + off) = bf162(h0, h1);
                    *(bf162*)(oL + off) =
                        bf162(__float2bfloat16_rn(x0 - __bfloat162float(h0)),
                              __float2bfloat16_rn(x1 - __bfloat162float(h1)));
                }
            }
        }
}

// ---------------------------------------------------------------------------
// Flash attention on mma.sync, bf16x3 both phases (S: 3 terms; PV: 3 terms).
// Block: (128 q rows, 1 head) = 8 warps x 16 rows. Grid 256 CTAs -> 2/SM.
// Smem: Qh@0 (16K), Ql@16K; 2 KV bufs @32K + b*32K: Kh,Kl,Vh,Vl (8K each).
// Total 96K/CTA -> 2 CTAs resident. Per-head KV (1MB) stays L2-resident.
// ---------------------------------------------------------------------------
#define ATTN_SMEM (32768 + 2 * 32768)

__global__ __launch_bounds__(256, 2) void attn_mma() {
    extern __shared__ char smem[];
    const uint32_t sbase = smem_u32(smem);
    const int h = blockIdx.y;
    const int row0 = blockIdx.x * 128;
    const int tid = threadIdx.x;
    const int lane = tid & 31;
    const int w = tid >> 5;

    const size_t hbase = (size_t)h * NTOK * DKH;

    load_tile<128>(sbase,         g_Qh + hbase + (size_t)row0 * DKH, DKH, tid);
    load_tile<128>(sbase + 16384, g_Ql + hbase + (size_t)row0 * DKH, DKH, tid);
    cp_commit();

    auto kvb = [&](int b) { return sbase + 32768 + b * 32768; };
    auto load_kv = [&](int t, int b) {
        size_t off = hbase + (size_t)t * 64 * DKH;
        uint32_t s0 = kvb(b);
        load_tile<64>(s0 +     0, g_Kh + off, DKH, tid);
        load_tile<64>(s0 +  8192, g_Kl + off, DKH, tid);
        load_tile<64>(s0 + 16384, g_Vh + off, DKH, tid);
        load_tile<64>(s0 + 24576, g_Vl + off, DKH, tid);
        cp_commit();
    };

    load_kv(0, 0);
    load_kv(1, 1);

    float m[2] = {-1e30f, -1e30f}, l[2] = {0.f, 0.f};
    float o[8][4];
#pragma unroll
    for (int nt = 0; nt < 8; nt++)
#pragma unroll
        for (int j = 0; j < 4; j++) o[nt][j] = 0.f;

    for (int i = 0; i < NTOK / 64; i++) {
        if (i < NTOK / 64 - 1) asm volatile("cp.async.wait_group 1;" ::: "memory");
        else                   asm volatile("cp.async.wait_group 0;" ::: "memory");
        __syncthreads();
        const uint32_t s0 = kvb(i & 1);

        // S = Q K^T  (1/sqrt(dk) folded into Q)  — bf16x3
        float sc[8][4];
#pragma unroll
        for (int nt = 0; nt < 8; nt++)
#pragma unroll
            for (int j = 0; j < 4; j++) sc[nt][j] = 0.f;

#pragma unroll
        for (int s = 0; s < 4; s++) {
            uint32_t kh[4][4], kl[4][4], qhf[4], qlf[4];
#pragma unroll
            for (int np = 0; np < 4; np++) {
                ldfragB(kh[np], s0,        np * 16, 2 * s, lane);
                ldfragB(kl[np], s0 + 8192, np * 16, 2 * s, lane);
            }
            ldfragA(qhf, sbase,         w * 16, 2 * s, lane);
            ldfragA(qlf, sbase + 16384, w * 16, 2 * s, lane);
#pragma unroll
            for (int np = 0; np < 4; np++)
#pragma unroll
                for (int hf = 0; hf < 2; hf++) {
                    int nt = np * 2 + hf;
                    mma_bf16(sc[nt], qhf, kh[np][2 * hf], kh[np][2 * hf + 1]);
                    mma_bf16(sc[nt], qhf, kl[np][2 * hf], kl[np][2 * hf + 1]);
                    mma_bf16(sc[nt], qlf, kh[np][2 * hf], kh[np][2 * hf + 1]);
                }
        }

        // online softmax (per row-half h2; quad shuffles)
#pragma unroll
        for (int h2 = 0; h2 < 2; h2++) {
            float mx = -1e30f;
#pragma unroll
            for (int nt = 0; nt < 8; nt++)
                mx = fmaxf(mx, fmaxf(sc[nt][2 * h2], sc[nt][2 * h2 + 1]));
            mx = fmaxf(mx, __shfl_xor_sync(0xffffffffu, mx, 1));
            mx = fmaxf(mx, __shfl_xor_sync(0xffffffffu, mx, 2));
            float mnew = fmaxf(m[h2], mx);
            float corr = exp2f((m[h2] - mnew) * LOG2E);
            m[h2] = mnew;
            float ls = 0.f;
#pragma unroll
            for (int nt = 0; nt < 8; nt++) {
                float p0 = exp2f((sc[nt][2 * h2]     - mnew) * LOG2E);
                float p1 = exp2f((sc[nt][2 * h2 + 1] - mnew) * LOG2E);
                sc[nt][2 * h2] = p0;
                sc[nt][2 * h2 + 1] = p1;
                ls += p0 + p1;
            }
            ls += __shfl_xor_sync(0xffffffffu, ls, 1);
            ls += __shfl_xor_sync(0xffffffffu, ls, 2);
            l[h2] = l[h2] * corr + ls;
#pragma unroll
            for (int nt = 0; nt < 8; nt++) {
                o[nt][2 * h2] *= corr;
                o[nt][2 * h2 + 1] *= corr;
            }
        }

        // O += P V  (P hi/lo x V hi/lo, 3 terms — Pl*Vh is REQUIRED)
#pragma unroll
        for (int s = 0; s < 4; s++) {
            uint32_t vh[4][4], vl[4][4];
#pragma unroll
            for (int tp = 0; tp < 4; tp++) {
                ldfragV(vh[tp], s0 + 16384, s * 16, 2 * tp, lane);
                ldfragV(vl[tp], s0 + 24576, s * 16, 2 * tp, lane);
            }
            uint32_t pah[4], pal[4];
#pragma unroll
            for (int j = 0; j < 4; j++) {
                int t = 2 * s + (j >> 1);
                float v0 = sc[t][(j & 1) * 2];
                float v1 = sc[t][(j & 1) * 2 + 1];
                bf16 h0 = __float2bfloat16_rn(v0);
                bf16 h1 = __float2bfloat16_rn(v1);
                bf162 ph = bf162(h0, h1);
                bf162 pl = bf162(__float2bfloat16_rn(v0 - __bfloat162float(h0)),
                                 __float2bfloat16_rn(v1 - __bfloat162float(h1)));
                pah[j] = *(uint32_t*)&ph;
                pal[j] = *(uint32_t*)&pl;
            }
#pragma unroll
            for (int tp = 0; tp < 4; tp++)
#pragma unroll
                for (int hf = 0; hf < 2; hf++) {
                    int nt = tp * 2 + hf;
                    mma_bf16(o[nt], pah, vh[tp][2 * hf], vh[tp][2 * hf + 1]);
                    mma_bf16(o[nt], pah, vl[tp][2 * hf], vl[tp][2 * hf + 1]);
                    mma_bf16(o[nt], pal, vh[tp][2 * hf], vh[tp][2 * hf + 1]);
                }
        }

        __syncthreads();
        // Refill the buffer stage i just vacated.
        if (i + 2 < NTOK / 64) load_kv(i + 2, i & 1);
    }

    // Epilogue: normalize, split hi/lo, write concat layout [row][h*64+col]
#pragma unroll
    for (int h2 = 0; h2 < 2; h2++) {
        float inv = 1.f / l[h2];
        int r = row0 + w * 16 + h2 * 8 + (lane >> 2);
#pragma unroll
        for (int nt = 0; nt < 8; nt++) {
            int col = nt * 8 + 2 * (lane & 3);
            float x0 = o[nt][2 * h2] * inv;
            float x1 = o[nt][2 * h2 + 1] * inv;
            bf16 h0 = __float2bfloat16_rn(x0);
            bf16 h1 = __float2bfloat16_rn(x1);
            size_t off = (size_t)r * DM + h * DKH + col;
            *(bf162*)(g_Ch + off) = bf162(h0, h1);
            *(bf162*)(g_Cl + off) =
                bf162(__float2bfloat16_rn(x0 - __bfloat162float(h0)),
                      __float2bfloat16_rn(x1 - __bfloat162float(h1)));
        }
    }
}

// ---------------------------------------------------------------------------
extern "C" void kernel_launch(void* const* d_in, const int* in_sizes, int n_in,
                              void* d_out, int out_size) {
    const float* q  = (const float*)d_in[0];
    const float* k  = (const float*)d_in[1];
    const float* v  = (const float*)d_in[2];
    const float* Wq = (const float*)d_in[3];
    const float* bq = (const float*)d_in[4];
    const float* Wk = (const float*)d_in[5];
    const float* bk = (const float*)d_in[6];
    const float* Wv = (const float*)d_in[7];
    const float* bv = (const float*)d_in[8];
    const float* Wo = (const float*)d_in[9];
    const float* bo = (const float*)d_in[10];
    float* out = (float*)d_out;

    bf16 *qh, *ql, *kh, *kl, *vh, *vl;
    bf16 *Wqh, *Wql, *Wkh, *Wkl, *Wvh, *Wvl, *Woh, *Wol;
    bf16 *Qh, *Ql, *Kh, *Kl, *Vh, *Vl, *Ch, *Cl;
    cudaGetSymbolAddress((void**)&qh, g_qh);   cudaGetSymbolAddress((void**)&ql, g_ql);
    cudaGetSymbolAddress((void**)&kh, g_kh);   cudaGetSymbolAddress((void**)&kl, g_kl);
    cudaGetSymbolAddress((void**)&vh, g_vh);   cudaGetSymbolAddress((void**)&vl, g_vl);
    cudaGetSymbolAddress((void**)&Wqh, g_Wqh); cudaGetSymbolAddress((void**)&Wql, g_Wql);
    cudaGetSymbolAddress((void**)&Wkh, g_Wkh); cudaGetSymbolAddress((void**)&Wkl, g_Wkl);
    cudaGetSymbolAddress((void**)&Wvh, g_Wvh); cudaGetSymbolAddress((void**)&Wvl, g_Wvl);
    cudaGetSymbolAddress((void**)&Woh, g_Woh); cudaGetSymbolAddress((void**)&Wol, g_Wol);
    cudaGetSymbolAddress((void**)&Qh, g_Qh);   cudaGetSymbolAddress((void**)&Ql, g_Ql);
    cudaGetSymbolAddress((void**)&Kh, g_Kh);   cudaGetSymbolAddress((void**)&Kl, g_Kl);
    cudaGetSymbolAddress((void**)&Vh, g_Vh);   cudaGetSymbolAddress((void**)&Vl, g_Vl);
    cudaGetSymbolAddress((void**)&Ch, g_Ch);   cudaGetSymbolAddress((void**)&Cl, g_Cl);

    cudaFuncSetAttribute(gemm_mma<0>, cudaFuncAttributeMaxDynamicSharedMemorySize, GEMM_SMEM);
    cudaFuncSetAttribute(gemm_mma<1>, cudaFuncAttributeMaxDynamicSharedMemorySize, GEMM_SMEM);
    cudaFuncSetAttribute(attn_mma, cudaFuncAttributeMaxDynamicSharedMemorySize, ATTN_SMEM);

    const int nQKV4 = NTOK * DM / 4;   // 524288
    const int nW4 = DM * DM / 4;       // 262144

    CvtJobs jobs;
    jobs.src[0] = q;  jobs.hi[0] = qh;  jobs.lo[0] = ql;  jobs.n4[0] = nQKV4;
    jobs.src[1] = k;  jobs.hi[1] = kh;  jobs.lo[1] = kl;  jobs.n4[1] = nQKV4;
    jobs.src[2] = v;  jobs.hi[2] = vh;  jobs.lo[2] = vl;  jobs.n4[2] = nQKV4;
    jobs.src[3] = Wq; jobs.hi[3] = Wqh; jobs.lo[3] = Wql; jobs.n4[3] = nW4;
    jobs.src[4] = Wk; jobs.hi[4] = Wkh; jobs.lo[4] = Wkl; jobs.n4[4] = nW4;
    jobs.src[5] = Wv; jobs.hi[5] = Wvh; jobs.lo[5] = Wvl; jobs.n4[5] = nW4;
    jobs.src[6] = Wo; jobs.hi[6] = Woh; jobs.lo[6] = Wol; jobs.n4[6] = nW4;
    cvt_all<<<dim3(nQKV4 / 1024, 7), 256>>>(jobs);

    dim3 gg(DM / 128, NTOK / 64);  // (8, 32) = 256 CTAs -> 2/SM
    gemm_mma<1><<<gg, 256, GEMM_SMEM>>>(qh, ql, Wqh, Wql, bq, nullptr, Qh, Ql, 0.125f);
    gemm_mma<1><<<gg, 256, GEMM_SMEM>>>(kh, kl, Wkh, Wkl, bk, nullptr, Kh, Kl, 1.0f);
    gemm_mma<1><<<gg, 256, GEMM_SMEM>>>(vh, vl, Wvh, Wvl, bv, nullptr, Vh, Vl, 1.0f);

    attn_mma<<<dim3(NTOK / 128, HEADS), 256, ATTN_SMEM>>>();

    gemm_mma<0><<<gg, 256, GEMM_SMEM>>>(Ch, Cl, Woh, Wol, bo, out, nullptr, nullptr, 1.0f);
}

// round 12
// speedup vs baseline: 1.3792x; 1.3792x over previous
#include <cuda_runtime.h>
#include <cuda_bf16.h>
#include <cuda_fp16.h>
#include <math.h>
#include <stdint.h>

#define NTOK 2048
#define DM 1024
#define HEADS 16
#define DKH 64
#define LOG2E 1.44269504f

typedef __nv_bfloat16 bf16;
typedef __nv_bfloat162 bf162;

// ---------------------------------------------------------------------------
// Scratch (__device__ globals; no allocs allowed)
// ---------------------------------------------------------------------------
__device__ __align__(128) bf16 g_qh[NTOK * DM], g_ql[NTOK * DM];
__device__ __align__(128) bf16 g_kh[NTOK * DM], g_kl[NTOK * DM];
__device__ __align__(128) bf16 g_vh[NTOK * DM], g_vl[NTOK * DM];
__device__ __align__(128) bf16 g_Wqh[DM * DM], g_Wql[DM * DM];
__device__ __align__(128) bf16 g_Wkh[DM * DM], g_Wkl[DM * DM];
__device__ __align__(128) bf16 g_Wvh[DM * DM], g_Wvl[DM * DM];
__device__ __align__(128) bf16 g_Woh[DM * DM], g_Wol[DM * DM];
// fp16 head-major projected Q/K/V (single precision level — fp16 rounding ~2^-11)
__device__ __align__(128) __half g_Qf[HEADS * NTOK * DKH];
__device__ __align__(128) __half g_Kf[HEADS * NTOK * DKH];
__device__ __align__(128) __half g_Vf[HEADS * NTOK * DKH];
// attention output (concat layout), bf16 hi/lo for the bf16x3 Wo GEMM
__device__ __align__(128) bf16 g_Ch[NTOK * DM], g_Cl[NTOK * DM];

// ---------------------------------------------------------------------------
// Warp MMA helpers (base compute_100 features only)
// ---------------------------------------------------------------------------
__device__ __forceinline__ uint32_t smem_u32(const void* p) {
    return (uint32_t)__cvta_generic_to_shared(p);
}

__device__ __forceinline__ void mma_bf16(float c[4], const uint32_t a[4],
                                         uint32_t b0, uint32_t b1) {
    asm volatile(
        "mma.sync.aligned.m16n8k16.row.col.f32.bf16.bf16.f32 "
        "{%0,%1,%2,%3}, {%4,%5,%6,%7}, {%8,%9}, {%0,%1,%2,%3};"
        : "+f"(c[0]), "+f"(c[1]), "+f"(c[2]), "+f"(c[3])
        : "r"(a[0]), "r"(a[1]), "r"(a[2]), "r"(a[3]), "r"(b0), "r"(b1));
}

__device__ __forceinline__ void mma_f16(float c[4], const uint32_t a[4],
                                        uint32_t b0, uint32_t b1) {
    asm volatile(
        "mma.sync.aligned.m16n8k16.row.col.f32.f16.f16.f32 "
        "{%0,%1,%2,%3}, {%4,%5,%6,%7}, {%8,%9}, {%0,%1,%2,%3};"
        : "+f"(c[0]), "+f"(c[1]), "+f"(c[2]), "+f"(c[3])
        : "r"(a[0]), "r"(a[1]), "r"(a[2]), "r"(a[3]), "r"(b0), "r"(b1));
}

__device__ __forceinline__ void ldmx4(uint32_t r[4], uint32_t addr) {
    asm volatile(
        "ldmatrix.sync.aligned.m8n8.x4.shared.b16 {%0,%1,%2,%3}, [%4];"
        : "=r"(r[0]), "=r"(r[1]), "=r"(r[2]), "=r"(r[3]) : "r"(addr));
}
__device__ __forceinline__ void ldmx4t(uint32_t r[4], uint32_t addr) {
    asm volatile(
        "ldmatrix.sync.aligned.m8n8.x4.trans.shared.b16 {%0,%1,%2,%3}, [%4];"
        : "=r"(r[0]), "=r"(r[1]), "=r"(r[2]), "=r"(r[3]) : "r"(addr));
}

// Tile format: [rows][64 x 16-bit], row pitch 128B, 16B chunk c swizzled: c^(r&7)
__device__ __forceinline__ uint32_t taddr(uint32_t base, int r, int c) {
    return base + r * 128 + (((uint32_t)(c ^ (r & 7))) << 4);
}

__device__ __forceinline__ void ldfragA(uint32_t f[4], uint32_t tb, int row0,
                                        int c0, int lane) {
    int grp = lane >> 3, lr = lane & 7;
    ldmx4(f, taddr(tb, row0 + (grp & 1) * 8 + lr, c0 + (grp >> 1)));
}
__device__ __forceinline__ void ldfragB(uint32_t f[4], uint32_t tb, int n0,
                                        int c0, int lane) {
    int grp = lane >> 3, lr = lane & 7;
    ldmx4(f, taddr(tb, n0 + (grp >> 1) * 8 + lr, c0 + (grp & 1)));
}
__device__ __forceinline__ void ldfragV(uint32_t f[4], uint32_t tb, int k0,
                                        int c0, int lane) {
    int grp = lane >> 3, lr = lane & 7;
    ldmx4t(f, taddr(tb, k0 + (grp & 1) * 8 + lr, c0 + (grp >> 1)));
}

template <int ROWS>
__device__ __forceinline__ void load_tile(uint32_t sbase, const void* gv,
                                          int pitch, int tid) {
    const bf16* g = (const bf16*)gv;  // 16-bit elements; only byte layout matters
#pragma unroll
    for (int i = 0; i < ROWS * 8 / 256; i++) {
        int idx = i * 256 + tid;
        int r = idx >> 3, c = idx & 7;
        uint32_t dst = taddr(sbase, r, c);
        const void* src = g + (size_t)r * pitch + c * 8;
        asm volatile("cp.async.cg.shared.global [%0], [%1], 16;"
                     :: "r"(dst), "l"(src) : "memory");
    }
}
__device__ __forceinline__ void cp_commit() {
    asm volatile("cp.async.commit_group;" ::: "memory");
}

// ---------------------------------------------------------------------------
// Batched fp32 -> (bf16 hi, bf16 lo) split: 7 jobs, 4 float4 per thread
// ---------------------------------------------------------------------------
struct CvtJobs {
    const float* src[7];
    bf16* hi[7];
    bf16* lo[7];
    int n4[7];
};

__global__ __launch_bounds__(256) void cvt_all(CvtJobs jobs) {
    const int j = blockIdx.y;
    const int n4 = jobs.n4[j];
    const int blk = blockIdx.x * 1024;
    if (blk >= n4) return;
    const int base = blk + threadIdx.x;
    const float4* src = (const float4*)jobs.src[j];

    float4 v[4];
#pragma unroll
    for (int u = 0; u < 4; u++) v[u] = src[base + u * 256];

#pragma unroll
    for (int u = 0; u < 4; u++) {
        int i = base + u * 256;
        bf16 h0 = __float2bfloat16_rn(v[u].x);
        bf16 h1 = __float2bfloat16_rn(v[u].y);
        bf16 h2 = __float2bfloat16_rn(v[u].z);
        bf16 h3 = __float2bfloat16_rn(v[u].w);
        bf162* hp = (bf162*)(jobs.hi[j] + i * 4);
        hp[0] = bf162(h0, h1);
        hp[1] = bf162(h2, h3);
        bf162* lp = (bf162*)(jobs.lo[j] + i * 4);
        lp[0] = bf162(__float2bfloat16_rn(v[u].x - __bfloat162float(h0)),
                      __float2bfloat16_rn(v[u].y - __bfloat162float(h1)));
        lp[1] = bf162(__float2bfloat16_rn(v[u].z - __bfloat162float(h2)),
                      __float2bfloat16_rn(v[u].w - __bfloat162float(h3)));
    }
}

// ---------------------------------------------------------------------------
// bf16x3 NT-GEMM on mma.sync. CTA tile 64x128, warp tile 32x32 (2x4 warps),
// k staged 64, 2-stage cp.async double buffer. 96KB smem -> 2 CTAs/SM.
// MODE 0: fp32 row-major out.  MODE 1: fp16 head-major out, * scale.
// ---------------------------------------------------------------------------
#define GEMM_STAGE 49152
#define GEMM_SMEM (2 * GEMM_STAGE)

template <int MODE>
__global__ __launch_bounds__(256, 2) void gemm_mma(
    const bf16* __restrict__ Ah, const bf16* __restrict__ Al,
    const bf16* __restrict__ Bh, const bf16* __restrict__ Bl,
    const float* __restrict__ bias, float* __restrict__ outF,
    __half* __restrict__ oF16, float scale) {
    extern __shared__ char smem[];
    const uint32_t sbase = smem_u32(smem);
    const int tid = threadIdx.x;
    const int lane = tid & 31;
    const int w = tid >> 5;
    const int wm = w >> 2, wn = w & 3;           // 2 x 4 warps -> 64 x 128
    const int bm = blockIdx.y * 64, bn = blockIdx.x * 128;

    auto load_stage = [&](int kt, int b) {
        uint32_t s0 = sbase + b * GEMM_STAGE;
        load_tile<64> (s0 +     0, Ah + (size_t)bm * DM + kt, DM, tid);
        load_tile<64> (s0 +  8192, Al + (size_t)bm * DM + kt, DM, tid);
        load_tile<128>(s0 + 16384, Bh + (size_t)bn * DM + kt, DM, tid);
        load_tile<128>(s0 + 32768, Bl + (size_t)bn * DM + kt, DM, tid);
        cp_commit();
    };

    float c[2][4][4];
#pragma unroll
    for (int i = 0; i < 2; i++)
#pragma unroll
        for (int j = 0; j < 4; j++)
#pragma unroll
            for (int k = 0; k < 4; k++) c[i][j][k] = 0.f;

    load_stage(0, 0);
    load_stage(64, 1);

    for (int it = 0; it < 16; it++) {
        if (it < 15) asm volatile("cp.async.wait_group 1;" ::: "memory");
        else         asm volatile("cp.async.wait_group 0;" ::: "memory");
        __syncthreads();

        uint32_t s0 = sbase + (it & 1) * GEMM_STAGE;
#pragma unroll
        for (int s = 0; s < 4; s++) {
            uint32_t aH[2][4], aL[2][4], bH[2][4], bL[2][4];
#pragma unroll
            for (int mt = 0; mt < 2; mt++) {
                ldfragA(aH[mt], s0,        wm * 32 + mt * 16, 2 * s, lane);
                ldfragA(aL[mt], s0 + 8192, wm * 32 + mt * 16, 2 * s, lane);
            }
#pragma unroll
            for (int np = 0; np < 2; np++) {
                ldfragB(bH[np], s0 + 16384, wn * 32 + np * 16, 2 * s, lane);
                ldfragB(bL[np], s0 + 32768, wn * 32 + np * 16, 2 * s, lane);
            }
#pragma unroll
            for (int mt = 0; mt < 2; mt++)
#pragma unroll
                for (int np = 0; np < 2; np++)
#pragma unroll
                    for (int hf = 0; hf < 2; hf++) {
                        int nt = np * 2 + hf;
                        mma_bf16(c[mt][nt], aH[mt], bH[np][2 * hf], bH[np][2 * hf + 1]);
                        mma_bf16(c[mt][nt], aH[mt], bL[np][2 * hf], bL[np][2 * hf + 1]);
                        mma_bf16(c[mt][nt], aL[mt], bH[np][2 * hf], bH[np][2 * hf + 1]);
                    }
        }
        __syncthreads();
        if (it + 2 < 16) load_stage((it + 2) * 64, it & 1);
    }

#pragma unroll
    for (int mt = 0; mt < 2; mt++)
#pragma unroll
        for (int nt = 0; nt < 4; nt++) {
            int r0 = bm + wm * 32 + mt * 16 + (lane >> 2);
            int col = bn + wn * 32 + nt * 8 + 2 * (lane & 3);
            float b0 = bias[col], b1 = bias[col + 1];
#pragma unroll
            for (int h2 = 0; h2 < 2; h2++) {
                int r = r0 + h2 * 8;
                float x0 = (c[mt][nt][2 * h2]     + b0) * scale;
                float x1 = (c[mt][nt][2 * h2 + 1] + b1) * scale;
                if (MODE == 0) {
                    float2 v = {x0, x1};
                    *(float2*)(outF + (size_t)r * DM + col) = v;
                } else {
                    size_t off = ((size_t)(col >> 6) * NTOK + r) * DKH + (col & 63);
                    *(__half2*)(oF16 + off) = __floats2half2_rn(x0, x1);
                }
            }
        }
}

// ---------------------------------------------------------------------------
// Flash attention on mma.sync, single-pass fp16 (S and PV one MMA term each).
// fp16 rounding ~2^-11 -> predicted attn-induced rel_err ~5e-4 (< 1e-3).
// Block: (256 q rows, 1 head) = 8 warps x 32 rows. Single wave (128 CTAs).
// Smem: Qf@0 (32K); 3 KV bufs @32K + b*16K: Kf (8K), Vf (8K). Total 80K.
// ---------------------------------------------------------------------------
#define ATTN_SMEM (32768 + 3 * 16384)

__global__ __launch_bounds__(256, 1) void attn_mma() {
    extern __shared__ char smem[];
    const uint32_t sbase = smem_u32(smem);
    const int h = blockIdx.y;
    const int row0 = blockIdx.x * 256;
    const int tid = threadIdx.x;
    const int lane = tid & 31;
    const int w = tid >> 5;

    const size_t hbase = (size_t)h * NTOK * DKH;

    load_tile<256>(sbase, g_Qf + hbase + (size_t)row0 * DKH, DKH, tid);
    cp_commit();

    auto kvb = [&](int b) { return sbase + 32768 + b * 16384; };
    auto load_kv = [&](int t, int b) {
        size_t off = hbase + (size_t)t * 64 * DKH;
        uint32_t s0 = kvb(b);
        load_tile<64>(s0 +    0, g_Kf + off, DKH, tid);
        load_tile<64>(s0 + 8192, g_Vf + off, DKH, tid);
        cp_commit();
    };

    load_kv(0, 0);
    load_kv(1, 1);

    float m[2][2], l[2][2];
    float o[2][8][4];
#pragma unroll
    for (int mt = 0; mt < 2; mt++) {
        m[mt][0] = m[mt][1] = -1e30f;
        l[mt][0] = l[mt][1] = 0.f;
#pragma unroll
        for (int nt = 0; nt < 8; nt++)
#pragma unroll
            for (int j = 0; j < 4; j++) o[mt][nt][j] = 0.f;
    }

    for (int i = 0; i < NTOK / 64; i++) {
        if (i < NTOK / 64 - 1) asm volatile("cp.async.wait_group 1;" ::: "memory");
        else                   asm volatile("cp.async.wait_group 0;" ::: "memory");
        __syncthreads();
        // prefetch stage i+2 into buffer (i+2)%3 (retired last iteration)
        if (i + 2 < NTOK / 64) load_kv(i + 2, (i + 2) % 3);

        const uint32_t s0 = kvb(i % 3);

        // S = Q K^T  (1/sqrt(dk) folded into Q) — single fp16 pass
        float sc[2][8][4];
#pragma unroll
        for (int mt = 0; mt < 2; mt++)
#pragma unroll
            for (int nt = 0; nt < 8; nt++)
#pragma unroll
                for (int j = 0; j < 4; j++) sc[mt][nt][j] = 0.f;

#pragma unroll
        for (int s = 0; s < 4; s++) {
            uint32_t kf[4][4], qf[2][4];
#pragma unroll
            for (int np = 0; np < 4; np++)
                ldfragB(kf[np], s0, np * 16, 2 * s, lane);
#pragma unroll
            for (int mt = 0; mt < 2; mt++)
                ldfragA(qf[mt], sbase, w * 32 + mt * 16, 2 * s, lane);
#pragma unroll
            for (int mt = 0; mt < 2; mt++)
#pragma unroll
                for (int np = 0; np < 4; np++)
#pragma unroll
                    for (int hf = 0; hf < 2; hf++)
                        mma_f16(sc[mt][np * 2 + hf], qf[mt],
                                kf[np][2 * hf], kf[np][2 * hf + 1]);
        }

        // online softmax (per mt, per row-half h2; quad shuffles)
#pragma unroll
        for (int mt = 0; mt < 2; mt++)
#pragma unroll
            for (int h2 = 0; h2 < 2; h2++) {
                float mx = -1e30f;
#pragma unroll
                for (int nt = 0; nt < 8; nt++)
                    mx = fmaxf(mx, fmaxf(sc[mt][nt][2 * h2], sc[mt][nt][2 * h2 + 1]));
                mx = fmaxf(mx, __shfl_xor_sync(0xffffffffu, mx, 1));
                mx = fmaxf(mx, __shfl_xor_sync(0xffffffffu, mx, 2));
                float mnew = fmaxf(m[mt][h2], mx);
                float corr = exp2f((m[mt][h2] - mnew) * LOG2E);
                m[mt][h2] = mnew;
                float ls = 0.f;
#pragma unroll
                for (int nt = 0; nt < 8; nt++) {
                    float p0 = exp2f((sc[mt][nt][2 * h2]     - mnew) * LOG2E);
                    float p1 = exp2f((sc[mt][nt][2 * h2 + 1] - mnew) * LOG2E);
                    sc[mt][nt][2 * h2] = p0;
                    sc[mt][nt][2 * h2 + 1] = p1;
                    ls += p0 + p1;
                }
                ls += __shfl_xor_sync(0xffffffffu, ls, 1);
                ls += __shfl_xor_sync(0xffffffffu, ls, 2);
                l[mt][h2] = l[mt][h2] * corr + ls;
#pragma unroll
                for (int nt = 0; nt < 8; nt++) {
                    o[mt][nt][2 * h2] *= corr;
                    o[mt][nt][2 * h2 + 1] *= corr;
                }
            }

        // O += P V — single fp16 pass (P fp16, V fp16)
#pragma unroll
        for (int s = 0; s < 4; s++) {
            uint32_t vf[4][4];
#pragma unroll
            for (int tp = 0; tp < 4; tp++)
                ldfragV(vf[tp], s0 + 8192, s * 16, 2 * tp, lane);
#pragma unroll
            for (int mt = 0; mt < 2; mt++) {
                uint32_t pa[4];
#pragma unroll
                for (int j = 0; j < 4; j++) {
                    int t = 2 * s + (j >> 1);
                    __half2 ph = __floats2half2_rn(sc[mt][t][(j & 1) * 2],
                                                   sc[mt][t][(j & 1) * 2 + 1]);
                    pa[j] = *(uint32_t*)&ph;
                }
#pragma unroll
                for (int tp = 0; tp < 4; tp++)
#pragma unroll
                    for (int hf = 0; hf < 2; hf++)
                        mma_f16(o[mt][tp * 2 + hf], pa,
                                vf[tp][2 * hf], vf[tp][2 * hf + 1]);
            }
        }
    }

    // Epilogue: normalize, split hi/lo, write concat layout [row][h*64+col]
#pragma unroll
    for (int mt = 0; mt < 2; mt++)
#pragma unroll
        for (int h2 = 0; h2 < 2; h2++) {
            float inv = 1.f / l[mt][h2];
            int r = row0 + w * 32 + mt * 16 + h2 * 8 + (lane >> 2);
#pragma unroll
            for (int nt = 0; nt < 8; nt++) {
                int col = nt * 8 + 2 * (lane & 3);
                float x0 = o[mt][nt][2 * h2] * inv;
                float x1 = o[mt][nt][2 * h2 + 1] * inv;
                bf16 h0 = __float2bfloat16_rn(x0);
                bf16 h1 = __float2bfloat16_rn(x1);
                size_t off = (size_t)r * DM + h * DKH + col;
                *(bf162*)(g_Ch + off) = bf162(h0, h1);
                *(bf162*)(g_Cl + off) =
                    bf162(__float2bfloat16_rn(x0 - __bfloat162float(h0)),
                          __float2bfloat16_rn(x1 - __bfloat162float(h1)));
            }
        }
}

// ---------------------------------------------------------------------------
extern "C" void kernel_launch(void* const* d_in, const int* in_sizes, int n_in,
                              void* d_out, int out_size) {
    const float* q  = (const float*)d_in[0];
    const float* k  = (const float*)d_in[1];
    const float* v  = (const float*)d_in[2];
    const float* Wq = (const float*)d_in[3];
    const float* bq = (const float*)d_in[4];
    const float* Wk = (const float*)d_in[5];
    const float* bk = (const float*)d_in[6];
    const float* Wv = (const float*)d_in[7];
    const float* bv = (const float*)d_in[8];
    const float* Wo = (const float*)d_in[9];
    const float* bo = (const float*)d_in[10];
    float* out = (float*)d_out;

    bf16 *qh, *ql, *kh, *kl, *vh, *vl;
    bf16 *Wqh, *Wql, *Wkh, *Wkl, *Wvh, *Wvl, *Woh, *Wol;
    bf16 *Ch, *Cl;
    __half *Qf, *Kf, *Vf;
    cudaGetSymbolAddress((void**)&qh, g_qh);   cudaGetSymbolAddress((void**)&ql, g_ql);
    cudaGetSymbolAddress((void**)&kh, g_kh);   cudaGetSymbolAddress((void**)&kl, g_kl);
    cudaGetSymbolAddress((void**)&vh, g_vh);   cudaGetSymbolAddress((void**)&vl, g_vl);
    cudaGetSymbolAddress((void**)&Wqh, g_Wqh); cudaGetSymbolAddress((void**)&Wql, g_Wql);
    cudaGetSymbolAddress((void**)&Wkh, g_Wkh); cudaGetSymbolAddress((void**)&Wkl, g_Wkl);
    cudaGetSymbolAddress((void**)&Wvh, g_Wvh); cudaGetSymbolAddress((void**)&Wvl, g_Wvl);
    cudaGetSymbolAddress((void**)&Woh, g_Woh); cudaGetSymbolAddress((void**)&Wol, g_Wol);
    cudaGetSymbolAddress((void**)&Qf, g_Qf);
    cudaGetSymbolAddress((void**)&Kf, g_Kf);
    cudaGetSymbolAddress((void**)&Vf, g_Vf);
    cudaGetSymbolAddress((void**)&Ch, g_Ch);   cudaGetSymbolAddress((void**)&Cl, g_Cl);

    cudaFuncSetAttribute(gemm_mma<0>, cudaFuncAttributeMaxDynamicSharedMemorySize, GEMM_SMEM);
    cudaFuncSetAttribute(gemm_mma<1>, cudaFuncAttributeMaxDynamicSharedMemorySize, GEMM_SMEM);
    cudaFuncSetAttribute(attn_mma, cudaFuncAttributeMaxDynamicSharedMemorySize, ATTN_SMEM);

    const int nQKV4 = NTOK * DM / 4;   // 524288
    const int nW4 = DM * DM / 4;       // 262144

    CvtJobs jobs;
    jobs.src[0] = q;  jobs.hi[0] = qh;  jobs.lo[0] = ql;  jobs.n4[0] = nQKV4;
    jobs.src[1] = k;  jobs.hi[1] = kh;  jobs.lo[1] = kl;  jobs.n4[1] = nQKV4;
    jobs.src[2] = v;  jobs.hi[2] = vh;  jobs.lo[2] = vl;  jobs.n4[2] = nQKV4;
    jobs.src[3] = Wq; jobs.hi[3] = Wqh; jobs.lo[3] = Wql; jobs.n4[3] = nW4;
    jobs.src[4] = Wk; jobs.hi[4] = Wkh; jobs.lo[4] = Wkl; jobs.n4[4] = nW4;
    jobs.src[5] = Wv; jobs.hi[5] = Wvh; jobs.lo[5] = Wvl; jobs.n4[5] = nW4;
    jobs.src[6] = Wo; jobs.hi[6] = Woh; jobs.lo[6] = Wol; jobs.n4[6] = nW4;
    cvt_all<<<dim3(nQKV4 / 1024, 7), 256>>>(jobs);

    dim3 gg(DM / 128, NTOK / 64);  // (8, 32) = 256 CTAs -> 2/SM
    gemm_mma<1><<<gg, 256, GEMM_SMEM>>>(qh, ql, Wqh, Wql, bq, nullptr, Qf, 0.125f);
    gemm_mma<1><<<gg, 256, GEMM_SMEM>>>(kh, kl, Wkh, Wkl, bk, nullptr, Kf, 1.0f);
    gemm_mma<1><<<gg, 256, GEMM_SMEM>>>(vh, vl, Wvh, Wvl, bv, nullptr, Vf, 1.0f);

    attn_mma<<<dim3(NTOK / 256, HEADS), 256, ATTN_SMEM>>>();

    gemm_mma<0><<<gg, 256, GEMM_SMEM>>>(Ch, Cl, Woh, Wol, bo, out, nullptr, 1.0f);
}

// round 13
// speedup vs baseline: 1.7182x; 1.2458x over previous
#include <cuda_runtime.h>
#include <cuda_fp16.h>
#include <math.h>
#include <stdint.h>

#define NTOK 2048
#define DM 1024
#define HEADS 16
#define DKH 64
#define LOG2E 1.44269504f

typedef __half fp16;
typedef __half2 fp162;

// ---------------------------------------------------------------------------
// Scratch (__device__ globals; no allocs allowed)
// ---------------------------------------------------------------------------
__device__ __align__(128) fp16 g_qf[NTOK * DM], g_kf[NTOK * DM], g_vf[NTOK * DM];
__device__ __align__(128) fp16 g_Wqh[DM * DM], g_Wql[DM * DM];
__device__ __align__(128) fp16 g_Wkh[DM * DM], g_Wkl[DM * DM];
__device__ __align__(128) fp16 g_Wvh[DM * DM], g_Wvl[DM * DM];
__device__ __align__(128) fp16 g_Woh[DM * DM], g_Wol[DM * DM];
// fp16 head-major projected Q/K/V
__device__ __align__(128) fp16 g_Qf[HEADS * NTOK * DKH];
__device__ __align__(128) fp16 g_Kf[HEADS * NTOK * DKH];
__device__ __align__(128) fp16 g_Vf[HEADS * NTOK * DKH];
// attention output (concat layout), single fp16
__device__ __align__(128) fp16 g_Cf[NTOK * DM];

// ---------------------------------------------------------------------------
// Warp MMA helpers (base compute_100 features only)
// ---------------------------------------------------------------------------
__device__ __forceinline__ uint32_t smem_u32(const void* p) {
    return (uint32_t)__cvta_generic_to_shared(p);
}

__device__ __forceinline__ void mma_f16(float c[4], const uint32_t a[4],
                                        uint32_t b0, uint32_t b1) {
    asm volatile(
        "mma.sync.aligned.m16n8k16.row.col.f32.f16.f16.f32 "
        "{%0,%1,%2,%3}, {%4,%5,%6,%7}, {%8,%9}, {%0,%1,%2,%3};"
        : "+f"(c[0]), "+f"(c[1]), "+f"(c[2]), "+f"(c[3])
        : "r"(a[0]), "r"(a[1]), "r"(a[2]), "r"(a[3]), "r"(b0), "r"(b1));
}

__device__ __forceinline__ void ldmx4(uint32_t r[4], uint32_t addr) {
    asm volatile(
        "ldmatrix.sync.aligned.m8n8.x4.shared.b16 {%0,%1,%2,%3}, [%4];"
        : "=r"(r[0]), "=r"(r[1]), "=r"(r[2]), "=r"(r[3]) : "r"(addr));
}
__device__ __forceinline__ void ldmx4t(uint32_t r[4], uint32_t addr) {
    asm volatile(
        "ldmatrix.sync.aligned.m8n8.x4.trans.shared.b16 {%0,%1,%2,%3}, [%4];"
        : "=r"(r[0]), "=r"(r[1]), "=r"(r[2]), "=r"(r[3]) : "r"(addr));
}

// Tile format: [rows][64 x 16-bit], row pitch 128B, 16B chunk c swizzled: c^(r&7)
__device__ __forceinline__ uint32_t taddr(uint32_t base, int r, int c) {
    return base + r * 128 + (((uint32_t)(c ^ (r & 7))) << 4);
}

__device__ __forceinline__ void ldfragA(uint32_t f[4], uint32_t tb, int row0,
                                        int c0, int lane) {
    int grp = lane >> 3, lr = lane & 7;
    ldmx4(f, taddr(tb, row0 + (grp & 1) * 8 + lr, c0 + (grp >> 1)));
}
__device__ __forceinline__ void ldfragB(uint32_t f[4], uint32_t tb, int n0,
                                        int c0, int lane) {
    int grp = lane >> 3, lr = lane & 7;
    ldmx4(f, taddr(tb, n0 + (grp >> 1) * 8 + lr, c0 + (grp & 1)));
}
__device__ __forceinline__ void ldfragV(uint32_t f[4], uint32_t tb, int k0,
                                        int c0, int lane) {
    int grp = lane >> 3, lr = lane & 7;
    ldmx4t(f, taddr(tb, k0 + (grp & 1) * 8 + lr, c0 + (grp >> 1)));
}

template <int ROWS>
__device__ __forceinline__ void load_tile(uint32_t sbase, const void* gv,
                                          int pitch, int tid) {
    const fp16* g = (const fp16*)gv;
#pragma unroll
    for (int i = 0; i < ROWS * 8 / 256; i++) {
        int idx = i * 256 + tid;
        int r = idx >> 3, c = idx & 7;
        uint32_t dst = taddr(sbase, r, c);
        const void* src = g + (size_t)r * pitch + c * 8;
        asm volatile("cp.async.cg.shared.global [%0], [%1], 16;"
                     :: "r"(dst), "l"(src) : "memory");
    }
}
__device__ __forceinline__ void cp_commit() {
    asm volatile("cp.async.commit_group;" ::: "memory");
}

// ---------------------------------------------------------------------------
// Batched fp32 -> fp16 conversions: 7 jobs; lo==null => single fp16,
// else (hi, lo) exact split (hi = fp16(x), lo = fp16(x - hi)).
// ---------------------------------------------------------------------------
struct CvtJobs {
    const float* src[7];
    fp16* hi[7];
    fp16* lo[7];
    int n4[7];
};

__global__ __launch_bounds__(256) void cvt_all(CvtJobs jobs) {
    const int j = blockIdx.y;
    const int n4 = jobs.n4[j];
    const int blk = blockIdx.x * 1024;
    if (blk >= n4) return;
    const int base = blk + threadIdx.x;
    const float4* src = (const float4*)jobs.src[j];
    fp16* hi = jobs.hi[j];
    fp16* lo = jobs.lo[j];

    float4 v[4];
#pragma unroll
    for (int u = 0; u < 4; u++) v[u] = src[base + u * 256];

#pragma unroll
    for (int u = 0; u < 4; u++) {
        int i = base + u * 256;
        fp162* hp = (fp162*)(hi + i * 4);
        if (lo == nullptr) {
            hp[0] = __floats2half2_rn(v[u].x, v[u].y);
            hp[1] = __floats2half2_rn(v[u].z, v[u].w);
        } else {
            fp16 h0 = __float2half_rn(v[u].x);
            fp16 h1 = __float2half_rn(v[u].y);
            fp16 h2 = __float2half_rn(v[u].z);
            fp16 h3 = __float2half_rn(v[u].w);
            hp[0] = fp162(h0, h1);
            hp[1] = fp162(h2, h3);
            fp162* lp = (fp162*)(lo + i * 4);
            lp[0] = __floats2half2_rn(v[u].x - __half2float(h0),
                                      v[u].y - __half2float(h1));
            lp[1] = __floats2half2_rn(v[u].z - __half2float(h2),
                                      v[u].w - __half2float(h3));
        }
    }
}

// ---------------------------------------------------------------------------
// 2-term fp16 NT-GEMM: D = A*(Wh+Wl)^T + bias. A single fp16 (only error
// source: A's input rounding ~2^-12). CTA tile 64x128, warp 32x32 (2x4),
// k staged 64, 2-stage double buffer. Stage: A@0 (8K), Bh@8K (16K), Bl@24K.
// Stage 40K -> 80K total -> 2 CTAs/SM.
// MODE 0: fp32 row-major out.  MODE 1: fp16 head-major out, * scale.
// ---------------------------------------------------------------------------
#define GEMM_STAGE 40960
#define GEMM_SMEM (2 * GEMM_STAGE)

template <int MODE>
__global__ __launch_bounds__(256, 2) void gemm_mma(
    const fp16* __restrict__ A,
    const fp16* __restrict__ Bh, const fp16* __restrict__ Bl,
    const float* __restrict__ bias, float* __restrict__ outF,
    fp16* __restrict__ oF16, float scale) {
    extern __shared__ char smem[];
    const uint32_t sbase = smem_u32(smem);
    const int tid = threadIdx.x;
    const int lane = tid & 31;
    const int w = tid >> 5;
    const int wm = w >> 2, wn = w & 3;           // 2 x 4 warps -> 64 x 128
    const int bm = blockIdx.y * 64, bn = blockIdx.x * 128;

    auto load_stage = [&](int kt, int b) {
        uint32_t s0 = sbase + b * GEMM_STAGE;
        load_tile<64> (s0 +     0, A  + (size_t)bm * DM + kt, DM, tid);
        load_tile<128>(s0 +  8192, Bh + (size_t)bn * DM + kt, DM, tid);
        load_tile<128>(s0 + 24576, Bl + (size_t)bn * DM + kt, DM, tid);
        cp_commit();
    };

    float c[2][4][4];
#pragma unroll
    for (int i = 0; i < 2; i++)
#pragma unroll
        for (int j = 0; j < 4; j++)
#pragma unroll
            for (int k = 0; k < 4; k++) c[i][j][k] = 0.f;

    load_stage(0, 0);
    load_stage(64, 1);

    for (int it = 0; it < 16; it++) {
        if (it < 15) asm volatile("cp.async.wait_group 1;" ::: "memory");
        else         asm volatile("cp.async.wait_group 0;" ::: "memory");
        __syncthreads();

        uint32_t s0 = sbase + (it & 1) * GEMM_STAGE;
#pragma unroll
        for (int s = 0; s < 4; s++) {
            uint32_t aF[2][4], bH[2][4], bL[2][4];
#pragma unroll
            for (int mt = 0; mt < 2; mt++)
                ldfragA(aF[mt], s0, wm * 32 + mt * 16, 2 * s, lane);
#pragma unroll
            for (int np = 0; np < 2; np++) {
                ldfragB(bH[np], s0 +  8192, wn * 32 + np * 16, 2 * s, lane);
                ldfragB(bL[np], s0 + 24576, wn * 32 + np * 16, 2 * s, lane);
            }
#pragma unroll
            for (int mt = 0; mt < 2; mt++)
#pragma unroll
                for (int np = 0; np < 2; np++)
#pragma unroll
                    for (int hf = 0; hf < 2; hf++) {
                        int nt = np * 2 + hf;
                        mma_f16(c[mt][nt], aF[mt], bH[np][2 * hf], bH[np][2 * hf + 1]);
                        mma_f16(c[mt][nt], aF[mt], bL[np][2 * hf], bL[np][2 * hf + 1]);
                    }
        }
        __syncthreads();
        if (it + 2 < 16) load_stage((it + 2) * 64, it & 1);
    }

#pragma unroll
    for (int mt = 0; mt < 2; mt++)
#pragma unroll
        for (int nt = 0; nt < 4; nt++) {
            int r0 = bm + wm * 32 + mt * 16 + (lane >> 2);
            int col = bn + wn * 32 + nt * 8 + 2 * (lane & 3);
            float b0 = bias[col], b1 = bias[col + 1];
#pragma unroll
            for (int h2 = 0; h2 < 2; h2++) {
                int r = r0 + h2 * 8;
                float x0 = (c[mt][nt][2 * h2]     + b0) * scale;
                float x1 = (c[mt][nt][2 * h2 + 1] + b1) * scale;
                if (MODE == 0) {
                    float2 v = {x0, x1};
                    *(float2*)(outF + (size_t)r * DM + col) = v;
                } else {
                    size_t off = ((size_t)(col >> 6) * NTOK + r) * DKH + (col & 63);
                    *(fp162*)(oF16 + off) = __floats2half2_rn(x0, x1);
                }
            }
        }
}

// ---------------------------------------------------------------------------
// Flash attention on mma.sync, single-pass fp16 (unchanged from R12 winner).
// Block: (256 q rows, 1 head) = 8 warps x 32 rows. Single wave (128 CTAs).
// Smem: Qf@0 (32K); 3 KV bufs @32K + b*16K: Kf (8K), Vf (8K). Total 80K.
// ---------------------------------------------------------------------------
#define ATTN_SMEM (32768 + 3 * 16384)

__global__ __launch_bounds__(256, 1) void attn_mma() {
    extern __shared__ char smem[];
    const uint32_t sbase = smem_u32(smem);
    const int h = blockIdx.y;
    const int row0 = blockIdx.x * 256;
    const int tid = threadIdx.x;
    const int lane = tid & 31;
    const int w = tid >> 5;

    const size_t hbase = (size_t)h * NTOK * DKH;

    load_tile<256>(sbase, g_Qf + hbase + (size_t)row0 * DKH, DKH, tid);
    cp_commit();

    auto kvb = [&](int b) { return sbase + 32768 + b * 16384; };
    auto load_kv = [&](int t, int b) {
        size_t off = hbase + (size_t)t * 64 * DKH;
        uint32_t s0 = kvb(b);
        load_tile<64>(s0 +    0, g_Kf + off, DKH, tid);
        load_tile<64>(s0 + 8192, g_Vf + off, DKH, tid);
        cp_commit();
    };

    load_kv(0, 0);
    load_kv(1, 1);

    float m[2][2], l[2][2];
    float o[2][8][4];
#pragma unroll
    for (int mt = 0; mt < 2; mt++) {
        m[mt][0] = m[mt][1] = -1e30f;
        l[mt][0] = l[mt][1] = 0.f;
#pragma unroll
        for (int nt = 0; nt < 8; nt++)
#pragma unroll
            for (int j = 0; j < 4; j++) o[mt][nt][j] = 0.f;
    }

    for (int i = 0; i < NTOK / 64; i++) {
        if (i < NTOK / 64 - 1) asm volatile("cp.async.wait_group 1;" ::: "memory");
        else                   asm volatile("cp.async.wait_group 0;" ::: "memory");
        __syncthreads();
        if (i + 2 < NTOK / 64) load_kv(i + 2, (i + 2) % 3);

        const uint32_t s0 = kvb(i % 3);

        // S = Q K^T  (1/sqrt(dk) folded into Q) — single fp16 pass
        float sc[2][8][4];
#pragma unroll
        for (int mt = 0; mt < 2; mt++)
#pragma unroll
            for (int nt = 0; nt < 8; nt++)
#pragma unroll
                for (int j = 0; j < 4; j++) sc[mt][nt][j] = 0.f;

#pragma unroll
        for (int s = 0; s < 4; s++) {
            uint32_t kf[4][4], qf[2][4];
#pragma unroll
            for (int np = 0; np < 4; np++)
                ldfragB(kf[np], s0, np * 16, 2 * s, lane);
#pragma unroll
            for (int mt = 0; mt < 2; mt++)
                ldfragA(qf[mt], sbase, w * 32 + mt * 16, 2 * s, lane);
#pragma unroll
            for (int mt = 0; mt < 2; mt++)
#pragma unroll
                for (int np = 0; np < 4; np++)
#pragma unroll
                    for (int hf = 0; hf < 2; hf++)
                        mma_f16(sc[mt][np * 2 + hf], qf[mt],
                                kf[np][2 * hf], kf[np][2 * hf + 1]);
        }

        // online softmax
#pragma unroll
        for (int mt = 0; mt < 2; mt++)
#pragma unroll
            for (int h2 = 0; h2 < 2; h2++) {
                float mx = -1e30f;
#pragma unroll
                for (int nt = 0; nt < 8; nt++)
                    mx = fmaxf(mx, fmaxf(sc[mt][nt][2 * h2], sc[mt][nt][2 * h2 + 1]));
                mx = fmaxf(mx, __shfl_xor_sync(0xffffffffu, mx, 1));
                mx = fmaxf(mx, __shfl_xor_sync(0xffffffffu, mx, 2));
                float mnew = fmaxf(m[mt][h2], mx);
                float corr = exp2f((m[mt][h2] - mnew) * LOG2E);
                m[mt][h2] = mnew;
                float ls = 0.f;
#pragma unroll
                for (int nt = 0; nt < 8; nt++) {
                    float p0 = exp2f((sc[mt][nt][2 * h2]     - mnew) * LOG2E);
                    float p1 = exp2f((sc[mt][nt][2 * h2 + 1] - mnew) * LOG2E);
                    sc[mt][nt][2 * h2] = p0;
                    sc[mt][nt][2 * h2 + 1] = p1;
                    ls += p0 + p1;
                }
                ls += __shfl_xor_sync(0xffffffffu, ls, 1);
                ls += __shfl_xor_sync(0xffffffffu, ls, 2);
                l[mt][h2] = l[mt][h2] * corr + ls;
#pragma unroll
                for (int nt = 0; nt < 8; nt++) {
                    o[mt][nt][2 * h2] *= corr;
                    o[mt][nt][2 * h2 + 1] *= corr;
                }
            }

        // O += P V — single fp16 pass
#pragma unroll
        for (int s = 0; s < 4; s++) {
            uint32_t vf[4][4];
#pragma unroll
            for (int tp = 0; tp < 4; tp++)
                ldfragV(vf[tp], s0 + 8192, s * 16, 2 * tp, lane);
#pragma unroll
            for (int mt = 0; mt < 2; mt++) {
                uint32_t pa[4];
#pragma unroll
                for (int j = 0; j < 4; j++) {
                    int t = 2 * s + (j >> 1);
                    fp162 ph = __floats2half2_rn(sc[mt][t][(j & 1) * 2],
                                                 sc[mt][t][(j & 1) * 2 + 1]);
                    pa[j] = *(uint32_t*)&ph;
                }
#pragma unroll
                for (int tp = 0; tp < 4; tp++)
#pragma unroll
                    for (int hf = 0; hf < 2; hf++)
                        mma_f16(o[mt][tp * 2 + hf], pa,
                                vf[tp][2 * hf], vf[tp][2 * hf + 1]);
            }
        }
    }

    // Epilogue: normalize, write concat layout [row][h*64+col] as single fp16
#pragma unroll
    for (int mt = 0; mt < 2; mt++)
#pragma unroll
        for (int h2 = 0; h2 < 2; h2++) {
            float inv = 1.f / l[mt][h2];
            int r = row0 + w * 32 + mt * 16 + h2 * 8 + (lane >> 2);
#pragma unroll
            for (int nt = 0; nt < 8; nt++) {
                int col = nt * 8 + 2 * (lane & 3);
                size_t off = (size_t)r * DM + h * DKH + col;
                *(fp162*)(g_Cf + off) =
                    __floats2half2_rn(o[mt][nt][2 * h2] * inv,
                                      o[mt][nt][2 * h2 + 1] * inv);
            }
        }
}

// ---------------------------------------------------------------------------
extern "C" void kernel_launch(void* const* d_in, const int* in_sizes, int n_in,
                              void* d_out, int out_size) {
    const float* q  = (const float*)d_in[0];
    const float* k  = (const float*)d_in[1];
    const float* v  = (const float*)d_in[2];
    const float* Wq = (const float*)d_in[3];
    const float* bq = (const float*)d_in[4];
    const float* Wk = (const float*)d_in[5];
    const float* bk = (const float*)d_in[6];
    const float* Wv = (const float*)d_in[7];
    const float* bv = (const float*)d_in[8];
    const float* Wo = (const float*)d_in[9];
    const float* bo = (const float*)d_in[10];
    float* out = (float*)d_out;

    fp16 *qf, *kf, *vf;
    fp16 *Wqh, *Wql, *Wkh, *Wkl, *Wvh, *Wvl, *Woh, *Wol;
    fp16 *Qf, *Kf, *Vf, *Cf;
    cudaGetSymbolAddress((void**)&qf, g_qf);
    cudaGetSymbolAddress((void**)&kf, g_kf);
    cudaGetSymbolAddress((void**)&vf, g_vf);
    cudaGetSymbolAddress((void**)&Wqh, g_Wqh); cudaGetSymbolAddress((void**)&Wql, g_Wql);
    cudaGetSymbolAddress((void**)&Wkh, g_Wkh); cudaGetSymbolAddress((void**)&Wkl, g_Wkl);
    cudaGetSymbolAddress((void**)&Wvh, g_Wvh); cudaGetSymbolAddress((void**)&Wvl, g_Wvl);
    cudaGetSymbolAddress((void**)&Woh, g_Woh); cudaGetSymbolAddress((void**)&Wol, g_Wol);
    cudaGetSymbolAddress((void**)&Qf, g_Qf);
    cudaGetSymbolAddress((void**)&Kf, g_Kf);
    cudaGetSymbolAddress((void**)&Vf, g_Vf);
    cudaGetSymbolAddress((void**)&Cf, g_Cf);

    cudaFuncSetAttribute(gemm_mma<0>, cudaFuncAttributeMaxDynamicSharedMemorySize, GEMM_SMEM);
    cudaFuncSetAttribute(gemm_mma<1>, cudaFuncAttributeMaxDynamicSharedMemorySize, GEMM_SMEM);
    cudaFuncSetAttribute(attn_mma, cudaFuncAttributeMaxDynamicSharedMemorySize, ATTN_SMEM);

    const int nQKV4 = NTOK * DM / 4;   // 524288
    const int nW4 = DM * DM / 4;       // 262144

    CvtJobs jobs;
    jobs.src[0] = q;  jobs.hi[0] = qf;  jobs.lo[0] = nullptr; jobs.n4[0] = nQKV4;
    jobs.src[1] = k;  jobs.hi[1] = kf;  jobs.lo[1] = nullptr; jobs.n4[1] = nQKV4;
    jobs.src[2] = v;  jobs.hi[2] = vf;  jobs.lo[2] = nullptr; jobs.n4[2] = nQKV4;
    jobs.src[3] = Wq; jobs.hi[3] = Wqh; jobs.lo[3] = Wql;     jobs.n4[3] = nW4;
    jobs.src[4] = Wk; jobs.hi[4] = Wkh; jobs.lo[4] = Wkl;     jobs.n4[4] = nW4;
    jobs.src[5] = Wv; jobs.hi[5] = Wvh; jobs.lo[5] = Wvl;     jobs.n4[5] = nW4;
    jobs.src[6] = Wo; jobs.hi[6] = Woh; jobs.lo[6] = Wol;     jobs.n4[6] = nW4;
    cvt_all<<<dim3(nQKV4 / 1024, 7), 256>>>(jobs);

    dim3 gg(DM / 128, NTOK / 64);  // (8, 32) = 256 CTAs -> 2/SM
    gemm_mma<1><<<gg, 256, GEMM_SMEM>>>(qf, Wqh, Wql, bq, nullptr, Qf, 0.125f);
    gemm_mma<1><<<gg, 256, GEMM_SMEM>>>(kf, Wkh, Wkl, bk, nullptr, Kf, 1.0f);
    gemm_mma<1><<<gg, 256, GEMM_SMEM>>>(vf, Wvh, Wvl, bv, nullptr, Vf, 1.0f);

    attn_mma<<<dim3(NTOK / 256, HEADS), 256, ATTN_SMEM>>>();

    gemm_mma<0><<<gg, 256, GEMM_SMEM>>>(Cf, Woh, Wol, bo, out, nullptr, 1.0f);
}

// round 14
// speedup vs baseline: 2.1996x; 1.2801x over previous
#include <cuda_runtime.h>
#include <cuda_fp16.h>
#include <math.h>
#include <stdint.h>

#define NTOK 2048
#define DM 1024
#define HEADS 16
#define DKH 64
#define LOG2E 1.44269504f

typedef __half fp16;
typedef __half2 fp162;

// ---------------------------------------------------------------------------
// Scratch (__device__ globals; no allocs allowed)
// ---------------------------------------------------------------------------
__device__ __align__(128) fp16 g_qf[NTOK * DM], g_kf[NTOK * DM], g_vf[NTOK * DM];
__device__ __align__(128) fp16 g_Wqf[DM * DM], g_Wkf[DM * DM];
__device__ __align__(128) fp16 g_Wvf[DM * DM], g_Wof[DM * DM];
// fp16 head-major projected Q/K/V
__device__ __align__(128) fp16 g_Qf[HEADS * NTOK * DKH];
__device__ __align__(128) fp16 g_Kf[HEADS * NTOK * DKH];
__device__ __align__(128) fp16 g_Vf[HEADS * NTOK * DKH];
// attention output (concat layout), single fp16
__device__ __align__(128) fp16 g_Cf[NTOK * DM];

// ---------------------------------------------------------------------------
// Warp MMA helpers (base compute_100 features only)
// ---------------------------------------------------------------------------
__device__ __forceinline__ uint32_t smem_u32(const void* p) {
    return (uint32_t)__cvta_generic_to_shared(p);
}

__device__ __forceinline__ void mma_f16(float c[4], const uint32_t a[4],
                                        uint32_t b0, uint32_t b1) {
    asm volatile(
        "mma.sync.aligned.m16n8k16.row.col.f32.f16.f16.f32 "
        "{%0,%1,%2,%3}, {%4,%5,%6,%7}, {%8,%9}, {%0,%1,%2,%3};"
        : "+f"(c[0]), "+f"(c[1]), "+f"(c[2]), "+f"(c[3])
        : "r"(a[0]), "r"(a[1]), "r"(a[2]), "r"(a[3]), "r"(b0), "r"(b1));
}

__device__ __forceinline__ void ldmx4(uint32_t r[4], uint32_t addr) {
    asm volatile(
        "ldmatrix.sync.aligned.m8n8.x4.shared.b16 {%0,%1,%2,%3}, [%4];"
        : "=r"(r[0]), "=r"(r[1]), "=r"(r[2]), "=r"(r[3]) : "r"(addr));
}
__device__ __forceinline__ void ldmx4t(uint32_t r[4], uint32_t addr) {
    asm volatile(
        "ldmatrix.sync.aligned.m8n8.x4.trans.shared.b16 {%0,%1,%2,%3}, [%4];"
        : "=r"(r[0]), "=r"(r[1]), "=r"(r[2]), "=r"(r[3]) : "r"(addr));
}

// Tile format: [rows][64 x 16-bit], row pitch 128B, 16B chunk c swizzled: c^(r&7)
__device__ __forceinline__ uint32_t taddr(uint32_t base, int r, int c) {
    return base + r * 128 + (((uint32_t)(c ^ (r & 7))) << 4);
}

__device__ __forceinline__ void ldfragA(uint32_t f[4], uint32_t tb, int row0,
                                        int c0, int lane) {
    int grp = lane >> 3, lr = lane & 7;
    ldmx4(f, taddr(tb, row0 + (grp & 1) * 8 + lr, c0 + (grp >> 1)));
}
__device__ __forceinline__ void ldfragB(uint32_t f[4], uint32_t tb, int n0,
                                        int c0, int lane) {
    int grp = lane >> 3, lr = lane & 7;
    ldmx4(f, taddr(tb, n0 + (grp >> 1) * 8 + lr, c0 + (grp & 1)));
}
__device__ __forceinline__ void ldfragV(uint32_t f[4], uint32_t tb, int k0,
                                        int c0, int lane) {
    int grp = lane >> 3, lr = lane & 7;
    ldmx4t(f, taddr(tb, k0 + (grp & 1) * 8 + lr, c0 + (grp >> 1)));
}

template <int ROWS>
__device__ __forceinline__ void load_tile(uint32_t sbase, const void* gv,
                                          int pitch, int tid) {
    const fp16* g = (const fp16*)gv;
#pragma unroll
    for (int i = 0; i < ROWS * 8 / 256; i++) {
        int idx = i * 256 + tid;
        int r = idx >> 3, c = idx & 7;
        uint32_t dst = taddr(sbase, r, c);
        const void* src = g + (size_t)r * pitch + c * 8;
        asm volatile("cp.async.cg.shared.global [%0], [%1], 16;"
                     :: "r"(dst), "l"(src) : "memory");
    }
}
__device__ __forceinline__ void cp_commit() {
    asm volatile("cp.async.commit_group;" ::: "memory");
}

// ---------------------------------------------------------------------------
// Batched fp32 -> fp16 conversion: 7 jobs, 4 float4 per thread
// ---------------------------------------------------------------------------
struct CvtJobs {
    const float* src[7];
    fp16* dst[7];
    int n4[7];
};

__global__ __launch_bounds__(256) void cvt_all(CvtJobs jobs) {
    const int j = blockIdx.y;
    const int n4 = jobs.n4[j];
    const int blk = blockIdx.x * 1024;
    if (blk >= n4) return;
    const int base = blk + threadIdx.x;
    const float4* src = (const float4*)jobs.src[j];
    fp16* dst = jobs.dst[j];

    float4 v[4];
#pragma unroll
    for (int u = 0; u < 4; u++) v[u] = src[base + u * 256];

#pragma unroll
    for (int u = 0; u < 4; u++) {
        int i = base + u * 256;
        fp162* dp = (fp162*)(dst + i * 4);
        dp[0] = __floats2half2_rn(v[u].x, v[u].y);
        dp[1] = __floats2half2_rn(v[u].z, v[u].w);
    }
}

// ---------------------------------------------------------------------------
// Single-pass fp16 NT-GEMM: D = A*W^T + bias. CTA tile 64x128, warp 32x32
// (2x4 warps), k staged 64, 2-stage double buffer. Stage: A@0 (8K), B@8K
// (16K). Stage 24K -> 48K total.
// MODE 0: fp32 row-major out.  MODE 1: fp16 head-major out, * scale.
// ---------------------------------------------------------------------------
#define GEMM_STAGE 24576
#define GEMM_SMEM (2 * GEMM_STAGE)

template <int MODE>
__global__ __launch_bounds__(256, 2) void gemm_mma(
    const fp16* __restrict__ A, const fp16* __restrict__ B,
    const float* __restrict__ bias, float* __restrict__ outF,
    fp16* __restrict__ oF16, float scale) {
    extern __shared__ char smem[];
    const uint32_t sbase = smem_u32(smem);
    const int tid = threadIdx.x;
    const int lane = tid & 31;
    const int w = tid >> 5;
    const int wm = w >> 2, wn = w & 3;           // 2 x 4 warps -> 64 x 128
    const int bm = blockIdx.y * 64, bn = blockIdx.x * 128;

    auto load_stage = [&](int kt, int b) {
        uint32_t s0 = sbase + b * GEMM_STAGE;
        load_tile<64> (s0 +    0, A + (size_t)bm * DM + kt, DM, tid);
        load_tile<128>(s0 + 8192, B + (size_t)bn * DM + kt, DM, tid);
        cp_commit();
    };

    float c[2][4][4];
#pragma unroll
    for (int i = 0; i < 2; i++)
#pragma unroll
        for (int j = 0; j < 4; j++)
#pragma unroll
            for (int k = 0; k < 4; k++) c[i][j][k] = 0.f;

    load_stage(0, 0);
    load_stage(64, 1);

    for (int it = 0; it < 16; it++) {
        if (it < 15) asm volatile("cp.async.wait_group 1;" ::: "memory");
        else         asm volatile("cp.async.wait_group 0;" ::: "memory");
        __syncthreads();

        uint32_t s0 = sbase + (it & 1) * GEMM_STAGE;
#pragma unroll
        for (int s = 0; s < 4; s++) {
            uint32_t aF[2][4], bF[2][4];
#pragma unroll
            for (int mt = 0; mt < 2; mt++)
                ldfragA(aF[mt], s0, wm * 32 + mt * 16, 2 * s, lane);
#pragma unroll
            for (int np = 0; np < 2; np++)
                ldfragB(bF[np], s0 + 8192, wn * 32 + np * 16, 2 * s, lane);
#pragma unroll
            for (int mt = 0; mt < 2; mt++)
#pragma unroll
                for (int np = 0; np < 2; np++)
#pragma unroll
                    for (int hf = 0; hf < 2; hf++)
                        mma_f16(c[mt][np * 2 + hf], aF[mt],
                                bF[np][2 * hf], bF[np][2 * hf + 1]);
        }
        __syncthreads();
        if (it + 2 < 16) load_stage((it + 2) * 64, it & 1);
    }

#pragma unroll
    for (int mt = 0; mt < 2; mt++)
#pragma unroll
        for (int nt = 0; nt < 4; nt++) {
            int r0 = bm + wm * 32 + mt * 16 + (lane >> 2);
            int col = bn + wn * 32 + nt * 8 + 2 * (lane & 3);
            float b0 = bias[col], b1 = bias[col + 1];
#pragma unroll
            for (int h2 = 0; h2 < 2; h2++) {
                int r = r0 + h2 * 8;
                float x0 = (c[mt][nt][2 * h2]     + b0) * scale;
                float x1 = (c[mt][nt][2 * h2 + 1] + b1) * scale;
                if (MODE == 0) {
                    float2 v = {x0, x1};
                    *(float2*)(outF + (size_t)r * DM + col) = v;
                } else {
                    size_t off = ((size_t)(col >> 6) * NTOK + r) * DKH + (col & 63);
                    *(fp162*)(oF16 + off) = __floats2half2_rn(x0, x1);
                }
            }
        }
}

// ---------------------------------------------------------------------------
// Flash attention on mma.sync, single-pass fp16 (unchanged from R12/R13).
// Block: (256 q rows, 1 head) = 8 warps x 32 rows. Single wave (128 CTAs).
// Smem: Qf@0 (32K); 3 KV bufs @32K + b*16K: Kf (8K), Vf (8K). Total 80K.
// ---------------------------------------------------------------------------
#define ATTN_SMEM (32768 + 3 * 16384)

__global__ __launch_bounds__(256, 1) void attn_mma() {
    extern __shared__ char smem[];
    const uint32_t sbase = smem_u32(smem);
    const int h = blockIdx.y;
    const int row0 = blockIdx.x * 256;
    const int tid = threadIdx.x;
    const int lane = tid & 31;
    const int w = tid >> 5;

    const size_t hbase = (size_t)h * NTOK * DKH;

    load_tile<256>(sbase, g_Qf + hbase + (size_t)row0 * DKH, DKH, tid);
    cp_commit();

    auto kvb = [&](int b) { return sbase + 32768 + b * 16384; };
    auto load_kv = [&](int t, int b) {
        size_t off = hbase + (size_t)t * 64 * DKH;
        uint32_t s0 = kvb(b);
        load_tile<64>(s0 +    0, g_Kf + off, DKH, tid);
        load_tile<64>(s0 + 8192, g_Vf + off, DKH, tid);
        cp_commit();
    };

    load_kv(0, 0);
    load_kv(1, 1);

    float m[2][2], l[2][2];
    float o[2][8][4];
#pragma unroll
    for (int mt = 0; mt < 2; mt++) {
        m[mt][0] = m[mt][1] = -1e30f;
        l[mt][0] = l[mt][1] = 0.f;
#pragma unroll
        for (int nt = 0; nt < 8; nt++)
#pragma unroll
            for (int j = 0; j < 4; j++) o[mt][nt][j] = 0.f;
    }

    for (int i = 0; i < NTOK / 64; i++) {
        if (i < NTOK / 64 - 1) asm volatile("cp.async.wait_group 1;" ::: "memory");
        else                   asm volatile("cp.async.wait_group 0;" ::: "memory");
        __syncthreads();
        if (i + 2 < NTOK / 64) load_kv(i + 2, (i + 2) % 3);

        const uint32_t s0 = kvb(i % 3);

        // S = Q K^T  (1/sqrt(dk) folded into Q) — single fp16 pass
        float sc[2][8][4];
#pragma unroll
        for (int mt = 0; mt < 2; mt++)
#pragma unroll
            for (int nt = 0; nt < 8; nt++)
#pragma unroll
                for (int j = 0; j < 4; j++) sc[mt][nt][j] = 0.f;

#pragma unroll
        for (int s = 0; s < 4; s++) {
            uint32_t kf[4][4], qf[2][4];
#pragma unroll
            for (int np = 0; np < 4; np++)
                ldfragB(kf[np], s0, np * 16, 2 * s, lane);
#pragma unroll
            for (int mt = 0; mt < 2; mt++)
                ldfragA(qf[mt], sbase, w * 32 + mt * 16, 2 * s, lane);
#pragma unroll
            for (int mt = 0; mt < 2; mt++)
#pragma unroll
                for (int np = 0; np < 4; np++)
#pragma unroll
                    for (int hf = 0; hf < 2; hf++)
                        mma_f16(sc[mt][np * 2 + hf], qf[mt],
                                kf[np][2 * hf], kf[np][2 * hf + 1]);
        }

        // online softmax
#pragma unroll
        for (int mt = 0; mt < 2; mt++)
#pragma unroll
            for (int h2 = 0; h2 < 2; h2++) {
                float mx = -1e30f;
#pragma unroll
                for (int nt = 0; nt < 8; nt++)
                    mx = fmaxf(mx, fmaxf(sc[mt][nt][2 * h2], sc[mt][nt][2 * h2 + 1]));
                mx = fmaxf(mx, __shfl_xor_sync(0xffffffffu, mx, 1));
                mx = fmaxf(mx, __shfl_xor_sync(0xffffffffu, mx, 2));
                float mnew = fmaxf(m[mt][h2], mx);
                float corr = exp2f((m[mt][h2] - mnew) * LOG2E);
                m[mt][h2] = mnew;
                float ls = 0.f;
#pragma unroll
                for (int nt = 0; nt < 8; nt++) {
                    float p0 = exp2f((sc[mt][nt][2 * h2]     - mnew) * LOG2E);
                    float p1 = exp2f((sc[mt][nt][2 * h2 + 1] - mnew) * LOG2E);
                    sc[mt][nt][2 * h2] = p0;
                    sc[mt][nt][2 * h2 + 1] = p1;
                    ls += p0 + p1;
                }
                ls += __shfl_xor_sync(0xffffffffu, ls, 1);
                ls += __shfl_xor_sync(0xffffffffu, ls, 2);
                l[mt][h2] = l[mt][h2] * corr + ls;
#pragma unroll
                for (int nt = 0; nt < 8; nt++) {
                    o[mt][nt][2 * h2] *= corr;
                    o[mt][nt][2 * h2 + 1] *= corr;
                }
            }

        // O += P V — single fp16 pass
#pragma unroll
        for (int s = 0; s < 4; s++) {
            uint32_t vf[4][4];
#pragma unroll
            for (int tp = 0; tp < 4; tp++)
                ldfragV(vf[tp], s0 + 8192, s * 16, 2 * tp, lane);
#pragma unroll
            for (int mt = 0; mt < 2; mt++) {
                uint32_t pa[4];
#pragma unroll
                for (int j = 0; j < 4; j++) {
                    int t = 2 * s + (j >> 1);
                    fp162 ph = __floats2half2_rn(sc[mt][t][(j & 1) * 2],
                                                 sc[mt][t][(j & 1) * 2 + 1]);
                    pa[j] = *(uint32_t*)&ph;
                }
#pragma unroll
                for (int tp = 0; tp < 4; tp++)
#pragma unroll
                    for (int hf = 0; hf < 2; hf++)
                        mma_f16(o[mt][tp * 2 + hf], pa,
                                vf[tp][2 * hf], vf[tp][2 * hf + 1]);
            }
        }
    }

    // Epilogue: normalize, write concat layout [row][h*64+col] as single fp16
#pragma unroll
    for (int mt = 0; mt < 2; mt++)
#pragma unroll
        for (int h2 = 0; h2 < 2; h2++) {
            float inv = 1.f / l[mt][h2];
            int r = row0 + w * 32 + mt * 16 + h2 * 8 + (lane >> 2);
#pragma unroll
            for (int nt = 0; nt < 8; nt++) {
                int col = nt * 8 + 2 * (lane & 3);
                size_t off = (size_t)r * DM + h * DKH + col;
                *(fp162*)(g_Cf + off) =
                    __floats2half2_rn(o[mt][nt][2 * h2] * inv,
                                      o[mt][nt][2 * h2 + 1] * inv);
            }
        }
}

// ---------------------------------------------------------------------------
extern "C" void kernel_launch(void* const* d_in, const int* in_sizes, int n_in,
                              void* d_out, int out_size) {
    const float* q  = (const float*)d_in[0];
    const float* k  = (const float*)d_in[1];
    const float* v  = (const float*)d_in[2];
    const float* Wq = (const float*)d_in[3];
    const float* bq = (const float*)d_in[4];
    const float* Wk = (const float*)d_in[5];
    const float* bk = (const float*)d_in[6];
    const float* Wv = (const float*)d_in[7];
    const float* bv = (const float*)d_in[8];
    const float* Wo = (const float*)d_in[9];
    const float* bo = (const float*)d_in[10];
    float* out = (float*)d_out;

    fp16 *qf, *kf, *vf, *Wqf, *Wkf, *Wvf, *Wof;
    fp16 *Qf, *Kf, *Vf, *Cf;
    cudaGetSymbolAddress((void**)&qf, g_qf);
    cudaGetSymbolAddress((void**)&kf, g_kf);
    cudaGetSymbolAddress((void**)&vf, g_vf);
    cudaGetSymbolAddress((void**)&Wqf, g_Wqf);
    cudaGetSymbolAddress((void**)&Wkf, g_Wkf);
    cudaGetSymbolAddress((void**)&Wvf, g_Wvf);
    cudaGetSymbolAddress((void**)&Wof, g_Wof);
    cudaGetSymbolAddress((void**)&Qf, g_Qf);
    cudaGetSymbolAddress((void**)&Kf, g_Kf);
    cudaGetSymbolAddress((void**)&Vf, g_Vf);
    cudaGetSymbolAddress((void**)&Cf, g_Cf);

    cudaFuncSetAttribute(gemm_mma<0>, cudaFuncAttributeMaxDynamicSharedMemorySize, GEMM_SMEM);
    cudaFuncSetAttribute(gemm_mma<1>, cudaFuncAttributeMaxDynamicSharedMemorySize, GEMM_SMEM);
    cudaFuncSetAttribute(attn_mma, cudaFuncAttributeMaxDynamicSharedMemorySize, ATTN_SMEM);

    const int nQKV4 = NTOK * DM / 4;   // 524288
    const int nW4 = DM * DM / 4;       // 262144

    CvtJobs jobs;
    jobs.src[0] = q;  jobs.dst[0] = qf;  jobs.n4[0] = nQKV4;
    jobs.src[1] = k;  jobs.dst[1] = kf;  jobs.n4[1] = nQKV4;
    jobs.src[2] = v;  jobs.dst[2] = vf;  jobs.n4[2] = nQKV4;
    jobs.src[3] = Wq; jobs.dst[3] = Wqf; jobs.n4[3] = nW4;
    jobs.src[4] = Wk; jobs.dst[4] = Wkf; jobs.n4[4] = nW4;
    jobs.src[5] = Wv; jobs.dst[5] = Wvf; jobs.n4[5] = nW4;
    jobs.src[6] = Wo; jobs.dst[6] = Wof; jobs.n4[6] = nW4;
    cvt_all<<<dim3(nQKV4 / 1024, 7), 256>>>(jobs);

    dim3 gg(DM / 128, NTOK / 64);  // (8, 32) = 256 CTAs -> 2/SM
    gemm_mma<1><<<gg, 256, GEMM_SMEM>>>(qf, Wqf, bq, nullptr, Qf, 0.125f);
    gemm_mma<1><<<gg, 256, GEMM_SMEM>>>(kf, Wkf, bk, nullptr, Kf, 1.0f);
    gemm_mma<1><<<gg, 256, GEMM_SMEM>>>(vf, Wvf, bv, nullptr, Vf, 1.0f);

    attn_mma<<<dim3(NTOK / 256, HEADS), 256, ATTN_SMEM>>>();

    gemm_mma<0><<<gg, 256, GEMM_SMEM>>>(Cf, Wof, bo, out, nullptr, 1.0f);
}

// round 16
// speedup vs baseline: 2.2201x; 1.0093x over previous
#include <cuda_runtime.h>
#include <cuda_fp16.h>
#include <math.h>
#include <stdint.h>

#define NTOK 2048
#define DM 1024
#define HEADS 16
#define DKH 64
#define LOG2E 1.44269504f

typedef __half fp16;
typedef __half2 fp162;

// ---------------------------------------------------------------------------
// Scratch (__device__ globals; no allocs allowed)
// ---------------------------------------------------------------------------
__device__ __align__(128) fp16 g_qf[NTOK * DM], g_kf[NTOK * DM], g_vf[NTOK * DM];
__device__ __align__(128) fp16 g_Wqf[DM * DM], g_Wkf[DM * DM];
__device__ __align__(128) fp16 g_Wvf[DM * DM], g_Wof[DM * DM];
__device__ __align__(128) fp16 g_Qf[HEADS * NTOK * DKH];
__device__ __align__(128) fp16 g_Kf[HEADS * NTOK * DKH];
__device__ __align__(128) fp16 g_Vf[HEADS * NTOK * DKH];
__device__ __align__(128) fp16 g_Cf[NTOK * DM];

// ---------------------------------------------------------------------------
// Warp MMA helpers (base compute_100 features only)
// ---------------------------------------------------------------------------
__device__ __forceinline__ uint32_t smem_u32(const void* p) {
    return (uint32_t)__cvta_generic_to_shared(p);
}

__device__ __forceinline__ void mma_f16(float c[4], const uint32_t a[4],
                                        uint32_t b0, uint32_t b1) {
    asm volatile(
        "mma.sync.aligned.m16n8k16.row.col.f32.f16.f16.f32 "
        "{%0,%1,%2,%3}, {%4,%5,%6,%7}, {%8,%9}, {%0,%1,%2,%3};"
        : "+f"(c[0]), "+f"(c[1]), "+f"(c[2]), "+f"(c[3])
        : "r"(a[0]), "r"(a[1]), "r"(a[2]), "r"(a[3]), "r"(b0), "r"(b1));
}

__device__ __forceinline__ void ldmx4(uint32_t r[4], uint32_t addr) {
    asm volatile(
        "ldmatrix.sync.aligned.m8n8.x4.shared.b16 {%0,%1,%2,%3}, [%4];"
        : "=r"(r[0]), "=r"(r[1]), "=r"(r[2]), "=r"(r[3]) : "r"(addr));
}
__device__ __forceinline__ void ldmx4t(uint32_t r[4], uint32_t addr) {
    asm volatile(
        "ldmatrix.sync.aligned.m8n8.x4.trans.shared.b16 {%0,%1,%2,%3}, [%4];"
        : "=r"(r[0]), "=r"(r[1]), "=r"(r[2]), "=r"(r[3]) : "r"(addr));
}

// Tile format: [rows][64 x 16-bit], row pitch 128B, 16B chunk c swizzled: c^(r&7)
__device__ __forceinline__ uint32_t taddr(uint32_t base, int r, int c) {
    return base + r * 128 + (((uint32_t)(c ^ (r & 7))) << 4);
}

__device__ __forceinline__ void ldfragA(uint32_t f[4], uint32_t tb, int row0,
                                        int c0, int lane) {
    int grp = lane >> 3, lr = lane & 7;
    ldmx4(f, taddr(tb, row0 + (grp & 1) * 8 + lr, c0 + (grp >> 1)));
}
__device__ __forceinline__ void ldfragB(uint32_t f[4], uint32_t tb, int n0,
                                        int c0, int lane) {
    int grp = lane >> 3, lr = lane & 7;
    ldmx4(f, taddr(tb, n0 + (grp >> 1) * 8 + lr, c0 + (grp & 1)));
}
__device__ __forceinline__ void ldfragV(uint32_t f[4], uint32_t tb, int k0,
                                        int c0, int lane) {
    int grp = lane >> 3, lr = lane & 7;
    ldmx4t(f, taddr(tb, k0 + (grp & 1) * 8 + lr, c0 + (grp >> 1)));
}

template <int ROWS>
__device__ __forceinline__ void load_tile(uint32_t sbase, const void* gv,
                                          int pitch, int tid) {
    const fp16* g = (const fp16*)gv;
#pragma unroll
    for (int i = 0; i < ROWS * 8 / 256; i++) {
        int idx = i * 256 + tid;
        int r = idx >> 3, c = idx & 7;
        uint32_t dst = taddr(sbase, r, c);
        const void* src = g + (size_t)r * pitch + c * 8;
        asm volatile("cp.async.cg.shared.global [%0], [%1], 16;"
                     :: "r"(dst), "l"(src) : "memory");
    }
}
__device__ __forceinline__ void cp_commit() {
    asm volatile("cp.async.commit_group;" ::: "memory");
}

// ---------------------------------------------------------------------------
// Batched fp32 -> fp16 conversion: 7 jobs, 4 float4 per thread
// ---------------------------------------------------------------------------
struct CvtJobs {
    const float* src[7];
    fp16* dst[7];
    int n4[7];
};

__global__ __launch_bounds__(256) void cvt_all(CvtJobs jobs) {
    const int j = blockIdx.y;
    const int n4 = jobs.n4[j];
    const int blk = blockIdx.x * 1024;
    if (blk >= n4) return;
    const int base = blk + threadIdx.x;
    const float4* src = (const float4*)jobs.src[j];
    fp16* dst = jobs.dst[j];

    float4 v[4];
#pragma unroll
    for (int u = 0; u < 4; u++) v[u] = src[base + u * 256];

#pragma unroll
    for (int u = 0; u < 4; u++) {
        int i = base + u * 256;
        fp162* dp = (fp162*)(dst + i * 4);
        dp[0] = __floats2half2_rn(v[u].x, v[u].y);
        dp[1] = __floats2half2_rn(v[u].z, v[u].w);
    }
}

// ---------------------------------------------------------------------------
// Single-pass fp16 NT-GEMM: D = A*W^T + bias. CTA tile 128x128, warp tile
// 64x32 (2x4 warps), k staged 64, 2-stage double buffer.
// Stage: A@0 (16K), B@16K (16K) -> 32K/stage, 64K total.
// MODE 0: fp32 row-major out.  MODE 1: fp16 head-major out, * scale.
// ---------------------------------------------------------------------------
#define GEMM_STAGE 32768
#define GEMM_SMEM (2 * GEMM_STAGE)

template <int MODE>
__global__ __launch_bounds__(256, 1) void gemm_mma(
    const fp16* __restrict__ A, const fp16* __restrict__ B,
    const float* __restrict__ bias, float* __restrict__ outF,
    fp16* __restrict__ oF16, float scale) {
    extern __shared__ char smem[];
    const uint32_t sbase = smem_u32(smem);
    const int tid = threadIdx.x;
    const int lane = tid & 31;
    const int w = tid >> 5;
    const int wm = w >> 2, wn = w & 3;           // 2 x 4 warps -> 128 x 128
    const int bm = blockIdx.y * 128, bn = blockIdx.x * 128;

    auto load_stage = [&](int kt, int b) {
        uint32_t s0 = sbase + b * GEMM_STAGE;
        load_tile<128>(s0 +     0, A + (size_t)bm * DM + kt, DM, tid);
        load_tile<128>(s0 + 16384, B + (size_t)bn * DM + kt, DM, tid);
        cp_commit();
    };

    float c[4][4][4];
#pragma unroll
    for (int i = 0; i < 4; i++)
#pragma unroll
        for (int j = 0; j < 4; j++)
#pragma unroll
            for (int k = 0; k < 4; k++) c[i][j][k] = 0.f;

    load_stage(0, 0);
    load_stage(64, 1);

    for (int it = 0; it < 16; it++) {
        if (it < 15) asm volatile("cp.async.wait_group 1;" ::: "memory");
        else         asm volatile("cp.async.wait_group 0;" ::: "memory");
        __syncthreads();

        uint32_t s0 = sbase + (it & 1) * GEMM_STAGE;
#pragma unroll
        for (int s = 0; s < 4; s++) {
            uint32_t aF[4][4], bF[2][4];
#pragma unroll
            for (int mt = 0; mt < 4; mt++)
                ldfragA(aF[mt], s0, wm * 64 + mt * 16, 2 * s, lane);
#pragma unroll
            for (int np = 0; np < 2; np++)
                ldfragB(bF[np], s0 + 16384, wn * 32 + np * 16, 2 * s, lane);
#pragma unroll
            for (int mt = 0; mt < 4; mt++)
#pragma unroll
                for (int np = 0; np < 2; np++)
#pragma unroll
                    for (int hf = 0; hf < 2; hf++)
                        mma_f16(c[mt][np * 2 + hf], aF[mt],
                                bF[np][2 * hf], bF[np][2 * hf + 1]);
        }
        __syncthreads();
        if (it + 2 < 16) load_stage((it + 2) * 64, it & 1);
    }

#pragma unroll
    for (int mt = 0; mt < 4; mt++)
#pragma unroll
        for (int nt = 0; nt < 4; nt++) {
            int r0 = bm + wm * 64 + mt * 16 + (lane >> 2);
            int col = bn + wn * 32 + nt * 8 + 2 * (lane & 3);
            float b0 = bias[col], b1 = bias[col + 1];
#pragma unroll
            for (int h2 = 0; h2 < 2; h2++) {
                int r = r0 + h2 * 8;
                float x0 = (c[mt][nt][2 * h2]     + b0) * scale;
                float x1 = (c[mt][nt][2 * h2 + 1] + b1) * scale;
                if (MODE == 0) {
                    float2 v = {x0, x1};
                    *(float2*)(outF + (size_t)r * DM + col) = v;
                } else {
                    size_t off = ((size_t)(col >> 6) * NTOK + r) * DKH + (col & 63);
                    *(fp162*)(oF16 + off) = __floats2half2_rn(x0, x1);
                }
            }
        }
}

// ---------------------------------------------------------------------------
// Flash attention on mma.sync, single-pass fp16 (unchanged from R14 winner).
// Block: (256 q rows, 1 head) = 8 warps x 32 rows. Single wave (128 CTAs).
// Smem: Qf@0 (32K); 3 KV bufs @32K + b*16K: Kf (8K), Vf (8K). Total 80K.
// ---------------------------------------------------------------------------
#define ATTN_SMEM (32768 + 3 * 16384)

__global__ __launch_bounds__(256, 1) void attn_mma() {
    extern __shared__ char smem[];
    const uint32_t sbase = smem_u32(smem);
    const int h = blockIdx.y;
    const int row0 = blockIdx.x * 256;
    const int tid = threadIdx.x;
    const int lane = tid & 31;
    const int w = tid >> 5;

    const size_t hbase = (size_t)h * NTOK * DKH;

    load_tile<256>(sbase, g_Qf + hbase + (size_t)row0 * DKH, DKH, tid);
    cp_commit();

    auto kvb = [&](int b) { return sbase + 32768 + b * 16384; };
    auto load_kv = [&](int t, int b) {
        size_t off = hbase + (size_t)t * 64 * DKH;
        uint32_t s0 = kvb(b);
        load_tile<64>(s0 +    0, g_Kf + off, DKH, tid);
        load_tile<64>(s0 + 8192, g_Vf + off, DKH, tid);
        cp_commit();
    };

    load_kv(0, 0);
    load_kv(1, 1);

    float m[2][2], l[2][2];
    float o[2][8][4];
#pragma unroll
    for (int mt = 0; mt < 2; mt++) {
        m[mt][0] = m[mt][1] = -1e30f;
        l[mt][0] = l[mt][1] = 0.f;
#pragma unroll
        for (int nt = 0; nt < 8; nt++)
#pragma unroll
            for (int j = 0; j < 4; j++) o[mt][nt][j] = 0.f;
    }

    for (int i = 0; i < NTOK / 64; i++) {
        if (i < NTOK / 64 - 1) asm volatile("cp.async.wait_group 1;" ::: "memory");
        else                   asm volatile("cp.async.wait_group 0;" ::: "memory");
        __syncthreads();
        if (i + 2 < NTOK / 64) load_kv(i + 2, (i + 2) % 3);

        const uint32_t s0 = kvb(i % 3);

        // S = Q K^T  (1/sqrt(dk) folded into Q) — single fp16 pass
        float sc[2][8][4];
#pragma unroll
        for (int mt = 0; mt < 2; mt++)
#pragma unroll
            for (int nt = 0; nt < 8; nt++)
#pragma unroll
                for (int j = 0; j < 4; j++) sc[mt][nt][j] = 0.f;

#pragma unroll
        for (int s = 0; s < 4; s++) {
            uint32_t kf[4][4], qf[2][4];
#pragma unroll
            for (int np = 0; np < 4; np++)
                ldfragB(kf[np], s0, np * 16, 2 * s, lane);
#pragma unroll
            for (int mt = 0; mt < 2; mt++)
                ldfragA(qf[mt], sbase, w * 32 + mt * 16, 2 * s, lane);
#pragma unroll
            for (int mt = 0; mt < 2; mt++)
#pragma unroll
                for (int np = 0; np < 4; np++)
#pragma unroll
                    for (int hf = 0; hf < 2; hf++)
                        mma_f16(sc[mt][np * 2 + hf], qf[mt],
                                kf[np][2 * hf], kf[np][2 * hf + 1]);
        }

        // online softmax
#pragma unroll
        for (int mt = 0; mt < 2; mt++)
#pragma unroll
            for (int h2 = 0; h2 < 2; h2++) {
                float mx = -1e30f;
#pragma unroll
                for (int nt = 0; nt < 8; nt++)
                    mx = fmaxf(mx, fmaxf(sc[mt][nt][2 * h2], sc[mt][nt][2 * h2 + 1]));
                mx = fmaxf(mx, __shfl_xor_sync(0xffffffffu, mx, 1));
                mx = fmaxf(mx, __shfl_xor_sync(0xffffffffu, mx, 2));
                float mnew = fmaxf(m[mt][h2], mx);
                float corr = exp2f((m[mt][h2] - mnew) * LOG2E);
                m[mt][h2] = mnew;
                float ls = 0.f;
#pragma unroll
                for (int nt = 0; nt < 8; nt++) {
                    float p0 = exp2f((sc[mt][nt][2 * h2]     - mnew) * LOG2E);
                    float p1 = exp2f((sc[mt][nt][2 * h2 + 1] - mnew) * LOG2E);
                    sc[mt][nt][2 * h2] = p0;
                    sc[mt][nt][2 * h2 + 1] = p1;
                    ls += p0 + p1;
                }
                ls += __shfl_xor_sync(0xffffffffu, ls, 1);
                ls += __shfl_xor_sync(0xffffffffu, ls, 2);
                l[mt][h2] = l[mt][h2] * corr + ls;
#pragma unroll
                for (int nt = 0; nt < 8; nt++) {
                    o[mt][nt][2 * h2] *= corr;
                    o[mt][nt][2 * h2 + 1] *= corr;
                }
            }

        // O += P V — single fp16 pass
#pragma unroll
        for (int s = 0; s < 4; s++) {
            uint32_t vf[4][4];
#pragma unroll
            for (int tp = 0; tp < 4; tp++)
                ldfragV(vf[tp], s0 + 8192, s * 16, 2 * tp, lane);
#pragma unroll
            for (int mt = 0; mt < 2; mt++) {
                uint32_t pa[4];
#pragma unroll
                for (int j = 0; j < 4; j++) {
                    int t = 2 * s + (j >> 1);
                    fp162 ph = __floats2half2_rn(sc[mt][t][(j & 1) * 2],
                                                 sc[mt][t][(j & 1) * 2 + 1]);
                    pa[j] = *(uint32_t*)&ph;
                }
#pragma unroll
                for (int tp = 0; tp < 4; tp++)
#pragma unroll
                    for (int hf = 0; hf < 2; hf++)
                        mma_f16(o[mt][tp * 2 + hf], pa,
                                vf[tp][2 * hf], vf[tp][2 * hf + 1]);
            }
        }
    }

    // Epilogue: normalize, write concat layout [row][h*64+col] as single fp16
#pragma unroll
    for (int mt = 0; mt < 2; mt++)
#pragma unroll
        for (int h2 = 0; h2 < 2; h2++) {
            float inv = 1.f / l[mt][h2];
            int r = row0 + w * 32 + mt * 16 + h2 * 8 + (lane >> 2);
#pragma unroll
            for (int nt = 0; nt < 8; nt++) {
                int col = nt * 8 + 2 * (lane & 3);
                size_t off = (size_t)r * DM + h * DKH + col;
                *(fp162*)(g_Cf + off) =
                    __floats2half2_rn(o[mt][nt][2 * h2] * inv,
                                      o[mt][nt][2 * h2 + 1] * inv);
            }
        }
}

// ---------------------------------------------------------------------------
extern "C" void kernel_launch(void* const* d_in, const int* in_sizes, int n_in,
                              void* d_out, int out_size) {
    const float* q  = (const float*)d_in[0];
    const float* k  = (const float*)d_in[1];
    const float* v  = (const float*)d_in[2];
    const float* Wq = (const float*)d_in[3];
    const float* bq = (const float*)d_in[4];
    const float* Wk = (const float*)d_in[5];
    const float* bk = (const float*)d_in[6];
    const float* Wv = (const float*)d_in[7];
    const float* bv = (const float*)d_in[8];
    const float* Wo = (const float*)d_in[9];
    const float* bo = (const float*)d_in[10];
    float* out = (float*)d_out;

    fp16 *qf, *kf, *vf, *Wqf, *Wkf, *Wvf, *Wof;
    fp16 *Qf, *Kf, *Vf, *Cf;
    cudaGetSymbolAddress((void**)&qf, g_qf);
    cudaGetSymbolAddress((void**)&kf, g_kf);
    cudaGetSymbolAddress((void**)&vf, g_vf);
    cudaGetSymbolAddress((void**)&Wqf, g_Wqf);
    cudaGetSymbolAddress((void**)&Wkf, g_Wkf);
    cudaGetSymbolAddress((void**)&Wvf, g_Wvf);
    cudaGetSymbolAddress((void**)&Wof, g_Wof);
    cudaGetSymbolAddress((void**)&Qf, g_Qf);
    cudaGetSymbolAddress((void**)&Kf, g_Kf);
    cudaGetSymbolAddress((void**)&Vf, g_Vf);
    cudaGetSymbolAddress((void**)&Cf, g_Cf);

    cudaFuncSetAttribute(gemm_mma<0>, cudaFuncAttributeMaxDynamicSharedMemorySize, GEMM_SMEM);
    cudaFuncSetAttribute(gemm_mma<1>, cudaFuncAttributeMaxDynamicSharedMemorySize, GEMM_SMEM);
    cudaFuncSetAttribute(attn_mma, cudaFuncAttributeMaxDynamicSharedMemorySize, ATTN_SMEM);

    const int nQKV4 = NTOK * DM / 4;   // 524288
    const int nW4 = DM * DM / 4;       // 262144

    CvtJobs jobs;
    jobs.src[0] = q;  jobs.dst[0] = qf;  jobs.n4[0] = nQKV4;
    jobs.src[1] = k;  jobs.dst[1] = kf;  jobs.n4[1] = nQKV4;
    jobs.src[2] = v;  jobs.dst[2] = vf;  jobs.n4[2] = nQKV4;
    jobs.src[3] = Wq; jobs.dst[3] = Wqf; jobs.n4[3] = nW4;
    jobs.src[4] = Wk; jobs.dst[4] = Wkf; jobs.n4[4] = nW4;
    jobs.src[5] = Wv; jobs.dst[5] = Wvf; jobs.n4[5] = nW4;
    jobs.src[6] = Wo; jobs.dst[6] = Wof; jobs.n4[6] = nW4;
    cvt_all<<<dim3(nQKV4 / 1024, 7), 256>>>(jobs);

    dim3 gg(DM / 128, NTOK / 128);  // (8, 16) = 128 CTAs, single wave
    gemm_mma<1><<<gg, 256, GEMM_SMEM>>>(qf, Wqf, bq, nullptr, Qf, 0.125f);
    gemm_mma<1><<<gg, 256, GEMM_SMEM>>>(kf, Wkf, bk, nullptr, Kf, 1.0f);
    gemm_mma<1><<<gg, 256, GEMM_SMEM>>>(vf, Wvf, bv, nullptr, Vf, 1.0f);

    attn_mma<<<dim3(NTOK / 256, HEADS), 256, ATTN_SMEM>>>();

    gemm_mma<0><<<gg, 256, GEMM_SMEM>>>(Cf, Wof, bo, out, nullptr, 1.0f);
}

// round 17
// speedup vs baseline: 2.3170x; 1.0437x over previous
#include <cuda_runtime.h>
#include <cuda_fp16.h>
#include <math.h>
#include <stdint.h>

#define NTOK 2048
#define DM 1024
#define HEADS 16
#define DKH 64
#define LOG2E 1.44269504f

typedef __half fp16;
typedef __half2 fp162;

// ---------------------------------------------------------------------------
// Scratch (__device__ globals; no allocs allowed)
// ---------------------------------------------------------------------------
__device__ __align__(128) fp16 g_qf[NTOK * DM], g_kf[NTOK * DM], g_vf[NTOK * DM];
__device__ __align__(128) fp16 g_Wqf[DM * DM], g_Wkf[DM * DM];
__device__ __align__(128) fp16 g_Wvf[DM * DM], g_Wof[DM * DM];
__device__ __align__(128) fp16 g_Qf[HEADS * NTOK * DKH];
__device__ __align__(128) fp16 g_Kf[HEADS * NTOK * DKH];
__device__ __align__(128) fp16 g_Vf[HEADS * NTOK * DKH];
__device__ __align__(128) fp16 g_Cf[NTOK * DM];

// ---------------------------------------------------------------------------
// Warp MMA helpers (base compute_100 features only)
// ---------------------------------------------------------------------------
__device__ __forceinline__ uint32_t smem_u32(const void* p) {
    return (uint32_t)__cvta_generic_to_shared(p);
}

__device__ __forceinline__ void mma_f16(float c[4], const uint32_t a[4],
                                        uint32_t b0, uint32_t b1) {
    asm volatile(
        "mma.sync.aligned.m16n8k16.row.col.f32.f16.f16.f32 "
        "{%0,%1,%2,%3}, {%4,%5,%6,%7}, {%8,%9}, {%0,%1,%2,%3};"
        : "+f"(c[0]), "+f"(c[1]), "+f"(c[2]), "+f"(c[3])
        : "r"(a[0]), "r"(a[1]), "r"(a[2]), "r"(a[3]), "r"(b0), "r"(b1));
}

__device__ __forceinline__ void ldmx4(uint32_t r[4], uint32_t addr) {
    asm volatile(
        "ldmatrix.sync.aligned.m8n8.x4.shared.b16 {%0,%1,%2,%3}, [%4];"
        : "=r"(r[0]), "=r"(r[1]), "=r"(r[2]), "=r"(r[3]) : "r"(addr));
}
__device__ __forceinline__ void ldmx4t(uint32_t r[4], uint32_t addr) {
    asm volatile(
        "ldmatrix.sync.aligned.m8n8.x4.trans.shared.b16 {%0,%1,%2,%3}, [%4];"
        : "=r"(r[0]), "=r"(r[1]), "=r"(r[2]), "=r"(r[3]) : "r"(addr));
}

// Tile format: [rows][64 x 16-bit], row pitch 128B, 16B chunk c swizzled: c^(r&7)
__device__ __forceinline__ uint32_t taddr(uint32_t base, int r, int c) {
    return base + r * 128 + (((uint32_t)(c ^ (r & 7))) << 4);
}

__device__ __forceinline__ void ldfragA(uint32_t f[4], uint32_t tb, int row0,
                                        int c0, int lane) {
    int grp = lane >> 3, lr = lane & 7;
    ldmx4(f, taddr(tb, row0 + (grp & 1) * 8 + lr, c0 + (grp >> 1)));
}
__device__ __forceinline__ void ldfragB(uint32_t f[4], uint32_t tb, int n0,
                                        int c0, int lane) {
    int grp = lane >> 3, lr = lane & 7;
    ldmx4(f, taddr(tb, n0 + (grp >> 1) * 8 + lr, c0 + (grp & 1)));
}
__device__ __forceinline__ void ldfragV(uint32_t f[4], uint32_t tb, int k0,
                                        int c0, int lane) {
    int grp = lane >> 3, lr = lane & 7;
    ldmx4t(f, taddr(tb, k0 + (grp & 1) * 8 + lr, c0 + (grp >> 1)));
}

template <int ROWS>
__device__ __forceinline__ void load_tile(uint32_t sbase, const void* gv,
                                          int pitch, int tid) {
    const fp16* g = (const fp16*)gv;
#pragma unroll
    for (int i = 0; i < ROWS * 8 / 256; i++) {
        int idx = i * 256 + tid;
        int r = idx >> 3, c = idx & 7;
        uint32_t dst = taddr(sbase, r, c);
        const void* src = g + (size_t)r * pitch + c * 8;
        asm volatile("cp.async.cg.shared.global [%0], [%1], 16;"
                     :: "r"(dst), "l"(src) : "memory");
    }
}
__device__ __forceinline__ void cp_commit() {
    asm volatile("cp.async.commit_group;" ::: "memory");
}

// ---------------------------------------------------------------------------
// Batched fp32 -> fp16 conversion: 7 jobs, 4 float4 per thread
// ---------------------------------------------------------------------------
struct CvtJobs {
    const float* src[7];
    fp16* dst[7];
    int n4[7];
};

__global__ __launch_bounds__(256) void cvt_all(CvtJobs jobs) {
    const int j = blockIdx.y;
    const int n4 = jobs.n4[j];
    const int blk = blockIdx.x * 1024;
    if (blk >= n4) return;
    const int base = blk + threadIdx.x;
    const float4* src = (const float4*)jobs.src[j];
    fp16* dst = jobs.dst[j];

    float4 v[4];
#pragma unroll
    for (int u = 0; u < 4; u++) v[u] = src[base + u * 256];

#pragma unroll
    for (int u = 0; u < 4; u++) {
        int i = base + u * 256;
        fp162* dp = (fp162*)(dst + i * 4);
        dp[0] = __floats2half2_rn(v[u].x, v[u].y);
        dp[1] = __floats2half2_rn(v[u].z, v[u].w);
    }
}

// ---------------------------------------------------------------------------
// Single-pass fp16 NT-GEMM: D = A*W^T + bias. CTA tile 128x128, warp tile
// 64x32 (2x4 warps), k staged 128 (8 iterations), 2-stage double buffer.
// Stage layout: A0@0 (16K, k 0-63), A1@16K (k 64-127), B0@32K, B1@48K.
// Stage 64K -> 128K total smem. Same k-order as R16 (bit-identical result);
// half the barrier/wait overhead per unit of compute.
// MODE 0: fp32 row-major out.  MODE 1: fp16 head-major out, * scale.
// ---------------------------------------------------------------------------
#define GEMM_STAGE 65536
#define GEMM_SMEM (2 * GEMM_STAGE)

template <int MODE>
__global__ __launch_bounds__(256, 1) void gemm_mma(
    const fp16* __restrict__ A, const fp16* __restrict__ B,
    const float* __restrict__ bias, float* __restrict__ outF,
    fp16* __restrict__ oF16, float scale) {
    extern __shared__ char smem[];
    const uint32_t sbase = smem_u32(smem);
    const int tid = threadIdx.x;
    const int lane = tid & 31;
    const int w = tid >> 5;
    const int wm = w >> 2, wn = w & 3;           // 2 x 4 warps -> 128 x 128
    const int bm = blockIdx.y * 128, bn = blockIdx.x * 128;

    auto load_stage = [&](int kt, int b) {
        uint32_t s0 = sbase + b * GEMM_STAGE;
        load_tile<128>(s0 +     0, A + (size_t)bm * DM + kt,      DM, tid);
        load_tile<128>(s0 + 16384, A + (size_t)bm * DM + kt + 64, DM, tid);
        load_tile<128>(s0 + 32768, B + (size_t)bn * DM + kt,      DM, tid);
        load_tile<128>(s0 + 49152, B + (size_t)bn * DM + kt + 64, DM, tid);
        cp_commit();
    };

    float c[4][4][4];
#pragma unroll
    for (int i = 0; i < 4; i++)
#pragma unroll
        for (int j = 0; j < 4; j++)
#pragma unroll
            for (int k = 0; k < 4; k++) c[i][j][k] = 0.f;

    load_stage(0, 0);
    load_stage(128, 1);

    for (int it = 0; it < 8; it++) {
        if (it < 7) asm volatile("cp.async.wait_group 1;" ::: "memory");
        else        asm volatile("cp.async.wait_group 0;" ::: "memory");
        __syncthreads();

        uint32_t s0 = sbase + (it & 1) * GEMM_STAGE;
#pragma unroll
        for (int s = 0; s < 8; s++) {
            const uint32_t sa = s0 + (s >> 2) * 16384;
            const uint32_t sb = s0 + 32768 + (s >> 2) * 16384;
            const int c0 = 2 * (s & 3);
            uint32_t aF[4][4], bF[2][4];
#pragma unroll
            for (int mt = 0; mt < 4; mt++)
                ldfragA(aF[mt], sa, wm * 64 + mt * 16, c0, lane);
#pragma unroll
            for (int np = 0; np < 2; np++)
                ldfragB(bF[np], sb, wn * 32 + np * 16, c0, lane);
#pragma unroll
            for (int mt = 0; mt < 4; mt++)
#pragma unroll
                for (int np = 0; np < 2; np++)
#pragma unroll
                    for (int hf = 0; hf < 2; hf++)
                        mma_f16(c[mt][np * 2 + hf], aF[mt],
                                bF[np][2 * hf], bF[np][2 * hf + 1]);
        }
        __syncthreads();
        if (it + 2 < 8) load_stage((it + 2) * 128, it & 1);
    }

#pragma unroll
    for (int mt = 0; mt < 4; mt++)
#pragma unroll
        for (int nt = 0; nt < 4; nt++) {
            int r0 = bm + wm * 64 + mt * 16 + (lane >> 2);
            int col = bn + wn * 32 + nt * 8 + 2 * (lane & 3);
            float b0 = bias[col], b1 = bias[col + 1];
#pragma unroll
            for (int h2 = 0; h2 < 2; h2++) {
                int r = r0 + h2 * 8;
                float x0 = (c[mt][nt][2 * h2]     + b0) * scale;
                float x1 = (c[mt][nt][2 * h2 + 1] + b1) * scale;
                if (MODE == 0) {
                    float2 v = {x0, x1};
                    *(float2*)(outF + (size_t)r * DM + col) = v;
                } else {
                    size_t off = ((size_t)(col >> 6) * NTOK + r) * DKH + (col & 63);
                    *(fp162*)(oF16 + off) = __floats2half2_rn(x0, x1);
                }
            }
        }
}

// ---------------------------------------------------------------------------
// Flash attention on mma.sync, single-pass fp16 (unchanged from R16 winner).
// Block: (256 q rows, 1 head) = 8 warps x 32 rows. Single wave (128 CTAs).
// Smem: Qf@0 (32K); 3 KV bufs @32K + b*16K: Kf (8K), Vf (8K). Total 80K.
// ---------------------------------------------------------------------------
#define ATTN_SMEM (32768 + 3 * 16384)

__global__ __launch_bounds__(256, 1) void attn_mma() {
    extern __shared__ char smem[];
    const uint32_t sbase = smem_u32(smem);
    const int h = blockIdx.y;
    const int row0 = blockIdx.x * 256;
    const int tid = threadIdx.x;
    const int lane = tid & 31;
    const int w = tid >> 5;

    const size_t hbase = (size_t)h * NTOK * DKH;

    load_tile<256>(sbase, g_Qf + hbase + (size_t)row0 * DKH, DKH, tid);
    cp_commit();

    auto kvb = [&](int b) { return sbase + 32768 + b * 16384; };
    auto load_kv = [&](int t, int b) {
        size_t off = hbase + (size_t)t * 64 * DKH;
        uint32_t s0 = kvb(b);
        load_tile<64>(s0 +    0, g_Kf + off, DKH, tid);
        load_tile<64>(s0 + 8192, g_Vf + off, DKH, tid);
        cp_commit();
    };

    load_kv(0, 0);
    load_kv(1, 1);

    float m[2][2], l[2][2];
    float o[2][8][4];
#pragma unroll
    for (int mt = 0; mt < 2; mt++) {
        m[mt][0] = m[mt][1] = -1e30f;
        l[mt][0] = l[mt][1] = 0.f;
#pragma unroll
        for (int nt = 0; nt < 8; nt++)
#pragma unroll
            for (int j = 0; j < 4; j++) o[mt][nt][j] = 0.f;
    }

    for (int i = 0; i < NTOK / 64; i++) {
        if (i < NTOK / 64 - 1) asm volatile("cp.async.wait_group 1;" ::: "memory");
        else                   asm volatile("cp.async.wait_group 0;" ::: "memory");
        __syncthreads();
        if (i + 2 < NTOK / 64) load_kv(i + 2, (i + 2) % 3);

        const uint32_t s0 = kvb(i % 3);

        // S = Q K^T  (1/sqrt(dk) folded into Q) — single fp16 pass
        float sc[2][8][4];
#pragma unroll
        for (int mt = 0; mt < 2; mt++)
#pragma unroll
            for (int nt = 0; nt < 8; nt++)
#pragma unroll
                for (int j = 0; j < 4; j++) sc[mt][nt][j] = 0.f;

#pragma unroll
        for (int s = 0; s < 4; s++) {
            uint32_t kf[4][4], qf[2][4];
#pragma unroll
            for (int np = 0; np < 4; np++)
                ldfragB(kf[np], s0, np * 16, 2 * s, lane);
#pragma unroll
            for (int mt = 0; mt < 2; mt++)
                ldfragA(qf[mt], sbase, w * 32 + mt * 16, 2 * s, lane);
#pragma unroll
            for (int mt = 0; mt < 2; mt++)
#pragma unroll
                for (int np = 0; np < 4; np++)
#pragma unroll
                    for (int hf = 0; hf < 2; hf++)
                        mma_f16(sc[mt][np * 2 + hf], qf[mt],
                                kf[np][2 * hf], kf[np][2 * hf + 1]);
        }

        // online softmax
#pragma unroll
        for (int mt = 0; mt < 2; mt++)
#pragma unroll
            for (int h2 = 0; h2 < 2; h2++) {
                float mx = -1e30f;
#pragma unroll
                for (int nt = 0; nt < 8; nt++)
                    mx = fmaxf(mx, fmaxf(sc[mt][nt][2 * h2], sc[mt][nt][2 * h2 + 1]));
                mx = fmaxf(mx, __shfl_xor_sync(0xffffffffu, mx, 1));
                mx = fmaxf(mx, __shfl_xor_sync(0xffffffffu, mx, 2));
                float mnew = fmaxf(m[mt][h2], mx);
                float corr = exp2f((m[mt][h2] - mnew) * LOG2E);
                m[mt][h2] = mnew;
                float ls = 0.f;
#pragma unroll
                for (int nt = 0; nt < 8; nt++) {
                    float p0 = exp2f((sc[mt][nt][2 * h2]     - mnew) * LOG2E);
                    float p1 = exp2f((sc[mt][nt][2 * h2 + 1] - mnew) * LOG2E);
                    sc[mt][nt][2 * h2] = p0;
                    sc[mt][nt][2 * h2 + 1] = p1;
                    ls += p0 + p1;
                }
                ls += __shfl_xor_sync(0xffffffffu, ls, 1);
                ls += __shfl_xor_sync(0xffffffffu, ls, 2);
                l[mt][h2] = l[mt][h2] * corr + ls;
#pragma unroll
                for (int nt = 0; nt < 8; nt++) {
                    o[mt][nt][2 * h2] *= corr;
                    o[mt][nt][2 * h2 + 1] *= corr;
                }
            }

        // O += P V — single fp16 pass
#pragma unroll
        for (int s = 0; s < 4; s++) {
            uint32_t vf[4][4];
#pragma unroll
            for (int tp = 0; tp < 4; tp++)
                ldfragV(vf[tp], s0 + 8192, s * 16, 2 * tp, lane);
#pragma unroll
            for (int mt = 0; mt < 2; mt++) {
                uint32_t pa[4];
#pragma unroll
                for (int j = 0; j < 4; j++) {
                    int t = 2 * s + (j >> 1);
                    fp162 ph = __floats2half2_rn(sc[mt][t][(j & 1) * 2],
                                                 sc[mt][t][(j & 1) * 2 + 1]);
                    pa[j] = *(uint32_t*)&ph;
                }
#pragma unroll
                for (int tp = 0; tp < 4; tp++)
#pragma unroll
                    for (int hf = 0; hf < 2; hf++)
                        mma_f16(o[mt][tp * 2 + hf], pa,
                                vf[tp][2 * hf], vf[tp][2 * hf + 1]);
            }
        }
    }

    // Epilogue: normalize, write concat layout [row][h*64+col] as single fp16
#pragma unroll
    for (int mt = 0; mt < 2; mt++)
#pragma unroll
        for (int h2 = 0; h2 < 2; h2++) {
            float inv = 1.f / l[mt][h2];
            int r = row0 + w * 32 + mt * 16 + h2 * 8 + (lane >> 2);
#pragma unroll
            for (int nt = 0; nt < 8; nt++) {
                int col = nt * 8 + 2 * (lane & 3);
                size_t off = (size_t)r * DM + h * DKH + col;
                *(fp162*)(g_Cf + off) =
                    __floats2half2_rn(o[mt][nt][2 * h2] * inv,
                                      o[mt][nt][2 * h2 + 1] * inv);
            }
        }
}

// ---------------------------------------------------------------------------
extern "C" void kernel_launch(void* const* d_in, const int* in_sizes, int n_in,
                              void* d_out, int out_size) {
    const float* q  = (const float*)d_in[0];
    const float* k  = (const float*)d_in[1];
    const float* v  = (const float*)d_in[2];
    const float* Wq = (const float*)d_in[3];
    const float* bq = (const float*)d_in[4];
    const float* Wk = (const float*)d_in[5];
    const float* bk = (const float*)d_in[6];
    const float* Wv = (const float*)d_in[7];
    const float* bv = (const float*)d_in[8];
    const float* Wo = (const float*)d_in[9];
    const float* bo = (const float*)d_in[10];
    float* out = (float*)d_out;

    fp16 *qf, *kf, *vf, *Wqf, *Wkf, *Wvf, *Wof;
    fp16 *Qf, *Kf, *Vf, *Cf;
    cudaGetSymbolAddress((void**)&qf, g_qf);
    cudaGetSymbolAddress((void**)&kf, g_kf);
    cudaGetSymbolAddress((void**)&vf, g_vf);
    cudaGetSymbolAddress((void**)&Wqf, g_Wqf);
    cudaGetSymbolAddress((void**)&Wkf, g_Wkf);
    cudaGetSymbolAddress((void**)&Wvf, g_Wvf);
    cudaGetSymbolAddress((void**)&Wof, g_Wof);
    cudaGetSymbolAddress((void**)&Qf, g_Qf);
    cudaGetSymbolAddress((void**)&Kf, g_Kf);
    cudaGetSymbolAddress((void**)&Vf, g_Vf);
    cudaGetSymbolAddress((void**)&Cf, g_Cf);

    cudaFuncSetAttribute(gemm_mma<0>, cudaFuncAttributeMaxDynamicSharedMemorySize, GEMM_SMEM);
    cudaFuncSetAttribute(gemm_mma<1>, cudaFuncAttributeMaxDynamicSharedMemorySize, GEMM_SMEM);
    cudaFuncSetAttribute(attn_mma, cudaFuncAttributeMaxDynamicSharedMemorySize, ATTN_SMEM);

    const int nQKV4 = NTOK * DM / 4;   // 524288
    const int nW4 = DM * DM / 4;       // 262144

    CvtJobs jobs;
    jobs.src[0] = q;  jobs.dst[0] = qf;  jobs.n4[0] = nQKV4;
    jobs.src[1] = k;  jobs.dst[1] = kf;  jobs.n4[1] = nQKV4;
    jobs.src[2] = v;  jobs.dst[2] = vf;  jobs.n4[2] = nQKV4;
    jobs.src[3] = Wq; jobs.dst[3] = Wqf; jobs.n4[3] = nW4;
    jobs.src[4] = Wk; jobs.dst[4] = Wkf; jobs.n4[4] = nW4;
    jobs.src[5] = Wv; jobs.dst[5] = Wvf; jobs.n4[5] = nW4;
    jobs.src[6] = Wo; jobs.dst[6] = Wof; jobs.n4[6] = nW4;
    cvt_all<<<dim3(nQKV4 / 1024, 7), 256>>>(jobs);

    dim3 gg(DM / 128, NTOK / 128);  // (8, 16) = 128 CTAs, single wave
    gemm_mma<1><<<gg, 256, GEMM_SMEM>>>(qf, Wqf, bq, nullptr, Qf, 0.125f);
    gemm_mma<1><<<gg, 256, GEMM_SMEM>>>(kf, Wkf, bk, nullptr, Kf, 1.0f);
    gemm_mma<1><<<gg, 256, GEMM_SMEM>>>(vf, Wvf, bv, nullptr, Vf, 1.0f);

    attn_mma<<<dim3(NTOK / 256, HEADS), 256, ATTN_SMEM>>>();

    gemm_mma<0><<<gg, 256, GEMM_SMEM>>>(Cf, Wof, bo, out, nullptr, 1.0f);
}